// round 12
// baseline (speedup 1.0000x reference)
#include <cuda_runtime.h>
#include <cuda_bf16.h>
#include <math.h>

#define B_  8
#define C_  512
#define T_  1024
#define E_  1024
#define H_  8
#define HD_ 64
#define QK_ 512
#define EV_ 128

// log(1024)/log(512)/sqrt(64) * log2(e)  (exp2-based softmax)
#define QSCALE_ 0.20037157933881626f

// ---------------- scratch (bf16 intermediates) ----------------
static __device__ __nv_bfloat16 g_u[(size_t)B_ * E_ * T_];
static __device__ __nv_bfloat16 g_v[(size_t)B_ * E_ * T_];
static __device__ __nv_bfloat16 g_q[(size_t)B_ * QK_ * T_];   // pre-scaled
static __device__ __nv_bfloat16 g_k[(size_t)B_ * QK_ * T_];
static __device__ __nv_bfloat16 g_w[(size_t)B_ * E_ * T_];
static __device__ float g_y[(size_t)B_ * C_ * T_];
static __device__ __nv_bfloat16 g_wi[(size_t)2 * E_ * C_];
static __device__ __nv_bfloat16 g_wa[(size_t)QK_ * C_];
static __device__ __nv_bfloat16 g_wo[(size_t)C_ * E_];
static __device__ __nv_bfloat16 g_xb[(size_t)B_ * C_ * T_];

// ---------------- helpers ----------------
__device__ __forceinline__ unsigned packbf(float lo, float hi) {
    unsigned r;
    asm("cvt.rn.bf16x2.f32 %0, %1, %2;" : "=r"(r) : "f"(hi), "f"(lo));
    return r;
}
__device__ __forceinline__ void mma_bf16(float* d, const unsigned* a, const unsigned* b) {
    asm volatile(
        "mma.sync.aligned.m16n8k16.row.col.f32.bf16.bf16.f32 "
        "{%0,%1,%2,%3}, {%4,%5,%6,%7}, {%8,%9}, {%0,%1,%2,%3};"
        : "+f"(d[0]), "+f"(d[1]), "+f"(d[2]), "+f"(d[3])
        : "r"(a[0]), "r"(a[1]), "r"(a[2]), "r"(a[3]), "r"(b[0]), "r"(b[1]));
}
__device__ __forceinline__ void ldsm4(unsigned& r0, unsigned& r1, unsigned& r2, unsigned& r3,
                                      unsigned addr) {
    asm volatile("ldmatrix.sync.aligned.m8n8.x4.shared.b16 {%0,%1,%2,%3}, [%4];"
                 : "=r"(r0), "=r"(r1), "=r"(r2), "=r"(r3) : "r"(addr));
}
__device__ __forceinline__ void ldsm4t(unsigned& r0, unsigned& r1, unsigned& r2, unsigned& r3,
                                       unsigned addr) {
    asm volatile("ldmatrix.sync.aligned.m8n8.x4.trans.shared.b16 {%0,%1,%2,%3}, [%4];"
                 : "=r"(r0), "=r"(r1), "=r"(r2), "=r"(r3) : "r"(addr));
}
__device__ __forceinline__ void cp16(unsigned saddr, const void* gptr) {
    asm volatile("cp.async.cg.shared.global [%0], [%1], 16;"
                 :: "r"(saddr), "l"(gptr));
}
#define CP_COMMIT() asm volatile("cp.async.commit_group;" ::: "memory")
#define CP_WAIT1()  asm volatile("cp.async.wait_group 1;" ::: "memory")
#define CP_WAIT2()  asm volatile("cp.async.wait_group 2;" ::: "memory")

// ---------------- fused fp32 -> bf16 conversion (all 4 tensors, 1 launch) ----
#define CV0 512
#define CV1 (CV0 + 128)
#define CV2 (CV1 + 256)
#define CV3 (CV2 + 2048)
__global__ __launch_bounds__(256) void conv_all(
    const float* __restrict__ s0, const float* __restrict__ s1,
    const float* __restrict__ s2, const float* __restrict__ s3)
{
    int blk = blockIdx.x;
    const float* src;
    __nv_bfloat16* dst;
    int rel;
    if      (blk < CV0) { src = s0; dst = g_wi; rel = blk; }
    else if (blk < CV1) { src = s1; dst = g_wa; rel = blk - CV0; }
    else if (blk < CV2) { src = s2; dst = g_wo; rel = blk - CV1; }
    else                { src = s3; dst = g_xb; rel = blk - CV2; }
    size_t i = ((size_t)rel * 256 + threadIdx.x) * 8;
    float4 a = *(const float4*)(src + i);
    float4 b = *(const float4*)(src + i + 4);
    uint4 w = {packbf(a.x, a.y), packbf(a.z, a.w), packbf(b.x, b.y), packbf(b.z, b.w)};
    *(uint4*)(dst + i) = w;
}

// ------- GEMM: 128x256 CTA tile, 64x64 warp tile, BK=32, 4-stage cp.async ----
#define ASTR 40
#define BSTR 264                      // 256 + 8 pad (row stride 528B, conflict-free)
#define ASZ (128 * ASTR)
#define BSZ (32 * BSTR)
#define GST 4
#define GEMM_SMEM ((GST * (ASZ + BSZ)) * 2)   // 108544 bytes

#define GEMM_DECL()                                                            \
    extern __shared__ __align__(16) unsigned short gsm[];                      \
    unsigned short* As = gsm;                                                  \
    unsigned short* Bs = gsm + GST * ASZ;                                      \
    const int b   = blockIdx.z;                                                \
    const int m0  = blockIdx.y * 128;                                          \
    const int n0  = blockIdx.x * 256;                                          \
    const int tid = threadIdx.x;                                               \
    const int lane = tid & 31, warp = tid >> 5;                                \
    const int g = lane >> 2, th4 = lane & 3;                                   \
    const int wm = (warp & 1) * 64, wn = (warp >> 1) * 64;                     \
    const unsigned as_b = (unsigned)__cvta_generic_to_shared(As);              \
    const unsigned bs_b = (unsigned)__cvta_generic_to_shared(Bs);              \
    const unsigned a_addr0 = as_b + ((wm + (lane & 15)) * ASTR + (lane >> 4) * 8) * 2; \
    const unsigned b_addr0 = bs_b + ((lane & 15) * BSTR + wn + (lane >> 4) * 8) * 2;   \
    float acc[4][8][4];                                                        \
    _Pragma("unroll") for (int i = 0; i < 4; i++)                              \
    _Pragma("unroll") for (int j = 0; j < 8; j++)                              \
    _Pragma("unroll") for (int r = 0; r < 4; r++) acc[i][j][r] = 0.f;

#define GEMM_CP(Wb, ldk, Xb, k0, st)                                           \
    _Pragma("unroll") for (int p = 0; p < 2; p++) {                            \
        int idx = tid + 256 * p;                                               \
        cp16(as_b + (st) * ASZ * 2 + ((idx >> 2) * ASTR + (idx & 3) * 8) * 2,  \
             (Wb) + (size_t)(m0 + (idx >> 2)) * (ldk) + (k0) + (idx & 3) * 8); \
    }                                                                          \
    _Pragma("unroll") for (int p = 0; p < 4; p++) {                            \
        int idx = tid + 256 * p;                                               \
        cp16(bs_b + (st) * BSZ * 2 + ((idx >> 5) * BSTR + (idx & 31) * 8) * 2, \
             (Xb) + (size_t)((k0) + (idx >> 5)) * T_ + n0 + (idx & 31) * 8);   \
    }

#define GEMM_COMPUTE(st)                                                       \
    _Pragma("unroll") for (int ks16 = 0; ks16 < 2; ks16++) {                   \
        unsigned af[4][4], bf[8][2];                                           \
        _Pragma("unroll") for (int mi = 0; mi < 4; mi++)                       \
            ldsm4(af[mi][0], af[mi][1], af[mi][2], af[mi][3],                  \
                  a_addr0 + (st) * ASZ * 2 + (mi * 16 * ASTR + ks16 * 16) * 2);\
        _Pragma("unroll") for (int nj = 0; nj < 4; nj++)                       \
            ldsm4t(bf[nj*2][0], bf[nj*2][1], bf[nj*2+1][0], bf[nj*2+1][1],     \
                   b_addr0 + (st) * BSZ * 2 + (ks16 * 16 * BSTR + nj * 16) * 2);\
        _Pragma("unroll") for (int mi = 0; mi < 4; mi++)                       \
        _Pragma("unroll") for (int ni = 0; ni < 8; ni++)                       \
            mma_bf16(acc[mi][ni], af[mi], bf[ni]);                             \
    }

#define GEMM_MAINLOOP(Wb, ldk, KK, Xb)                                         \
    {                                                                          \
        const int nit = (KK) / 32;                                             \
        GEMM_CP(Wb, ldk, Xb, 0, 0);  CP_COMMIT();                              \
        GEMM_CP(Wb, ldk, Xb, 32, 1); CP_COMMIT();                              \
        GEMM_CP(Wb, ldk, Xb, 64, 2); CP_COMMIT();                              \
        for (int it = 0; it < nit; it++) {                                     \
            CP_WAIT2();                                                        \
            __syncthreads();                                                   \
            if (it + 3 < nit) { GEMM_CP(Wb, ldk, Xb, (it + 3) * 32, (it + 3) & 3); } \
            CP_COMMIT();                                                       \
            GEMM_COMPUTE(it & 3);                                              \
        }                                                                      \
    }

// =============================================================================
// GEMM1: u,v = silu(W_in @ x + b_in) -> bf16   M=2048 K=512 N=1024
// =============================================================================
__global__ __launch_bounds__(256) void gemm_uv_bf16(const float* __restrict__ bias)
{
    GEMM_DECL();
    const __nv_bfloat16* xb = g_xb + (size_t)b * C_ * T_;
    GEMM_MAINLOOP(g_wi, C_, C_, xb);
    __nv_bfloat16* outp = (m0 < E_)
        ? g_u + (size_t)b * E_ * T_
        : g_v + (size_t)b * E_ * T_ - (size_t)E_ * T_;
#pragma unroll
    for (int mi = 0; mi < 4; mi++) {
        int m = m0 + wm + mi * 16 + g;
        float b0 = bias[m], b1 = bias[m + 8];
#pragma unroll
        for (int ni = 0; ni < 8; ni++) {
            int n = n0 + wn + ni * 8 + 2 * th4;
            float t0 = acc[mi][ni][0] + b0, t1 = acc[mi][ni][1] + b0;
            float t2 = acc[mi][ni][2] + b1, t3 = acc[mi][ni][3] + b1;
            unsigned w0 = packbf(t0 / (1.f + __expf(-t0)), t1 / (1.f + __expf(-t1)));
            unsigned w1 = packbf(t2 / (1.f + __expf(-t2)), t3 / (1.f + __expf(-t3)));
            *(unsigned*)(outp + (size_t)m * T_ + n)       = w0;
            *(unsigned*)(outp + (size_t)(m + 8) * T_ + n) = w1;
        }
    }
}

// =============================================================================
// GEMM2: z = W_attn @ x + b_attn; q=(z*wq+bq)*QSCALE, k=z*wk+bk -> bf16
// =============================================================================
__global__ __launch_bounds__(256) void gemm_qk_bf16(
    const float* __restrict__ bias,
    const float* __restrict__ wq, const float* __restrict__ bq,
    const float* __restrict__ wk, const float* __restrict__ bk)
{
    GEMM_DECL();
    const __nv_bfloat16* xb = g_xb + (size_t)b * C_ * T_;
    GEMM_MAINLOOP(g_wa, C_, C_, xb);
    __nv_bfloat16* qp = g_q + (size_t)b * QK_ * T_;
    __nv_bfloat16* kp = g_k + (size_t)b * QK_ * T_;
#pragma unroll
    for (int mi = 0; mi < 4; mi++) {
        int m = m0 + wm + mi * 16 + g;
        float bi0 = bias[m], bi1 = bias[m + 8];
        float wq0 = wq[m] * QSCALE_, bq0 = bq[m] * QSCALE_;
        float wk0 = wk[m], bk0 = bk[m];
        float wq1 = wq[m + 8] * QSCALE_, bq1 = bq[m + 8] * QSCALE_;
        float wk1 = wk[m + 8], bk1 = bk[m + 8];
#pragma unroll
        for (int ni = 0; ni < 8; ni++) {
            int n = n0 + wn + ni * 8 + 2 * th4;
            float z0 = acc[mi][ni][0] + bi0, z1 = acc[mi][ni][1] + bi0;
            float z2 = acc[mi][ni][2] + bi1, z3 = acc[mi][ni][3] + bi1;
            *(unsigned*)(qp + (size_t)m * T_ + n)       = packbf(z0 * wq0 + bq0, z1 * wq0 + bq0);
            *(unsigned*)(qp + (size_t)(m + 8) * T_ + n) = packbf(z2 * wq1 + bq1, z3 * wq1 + bq1);
            *(unsigned*)(kp + (size_t)m * T_ + n)       = packbf(z0 * wk0 + bk0, z1 * wk0 + bk0);
            *(unsigned*)(kp + (size_t)(m + 8) * T_ + n) = packbf(z2 * wk1 + bk1, z3 * wk1 + bk1);
        }
    }
}

// =============================================================================
// Flash attention bf16, BQ=128 (8 warps x 16 rows), BKV=64,
// 2-stage cp.async KV pipeline, no-max exp2 softmax, fused u-gating epilogue.
// __launch_bounds__(256,2): regs<=128 so 2 CTAs/SM. (R10 structure, unchanged.)
// =============================================================================
#define QS2 136
#define KS2 72
#define KVB (192 * KS2 * 2)
#define QS_BYTES (64 * QS2 * 2)
#define ATTN_SMEM (QS_BYTES + 2 * KVB)

__global__ __launch_bounds__(256, 2) void attn_bf16_kernel()
{
    extern __shared__ __align__(16) char dsm[];
    unsigned short* qs = (unsigned short*)dsm;
    unsigned short* ks = (unsigned short*)(dsm + QS_BYTES);
    unsigned short* vs = ks + 64 * KS2;
    float* os = (float*)(dsm + QS_BYTES);   // epilogue alias

    const int b  = blockIdx.z;
    const int h  = blockIdx.y;
    const int qt = blockIdx.x;
    const int tid = threadIdx.x;
    const int lane = tid & 31, warp = tid >> 5;
    const int g = lane >> 2, th4 = lane & 3;
    const int wq = warp * 16;

    const __nv_bfloat16* qbase = g_q + (size_t)(b * QK_ + h * HD_) * T_;
    const __nv_bfloat16* kbase = g_k + (size_t)(b * QK_ + h * HD_) * T_;
    const __nv_bfloat16* vbase = g_v + (size_t)(b * E_ + h * EV_) * T_;

    const unsigned qs_b = (unsigned)__cvta_generic_to_shared(qs);
    const unsigned ks_b = (unsigned)__cvta_generic_to_shared(ks);
    const unsigned vs_b = (unsigned)__cvta_generic_to_shared(vs);

    const unsigned qa0 = qs_b + ((((lane >> 4) << 3) + (lane & 7)) * QS2 + wq + (lane & 8)) * 2;
    const unsigned ka0 = ks_b + (((lane & 7) + ((lane >> 3) & 1) * 8) * KS2 + ((lane >> 4) & 1) * 8) * 2;
    const unsigned va0 = vs_b + (((lane & 7) + ((lane >> 4) & 1) * 8) * KS2 + (lane & 8)) * 2;

#pragma unroll
    for (int p = 0; p < 4; p++) {
        int idx = tid + 256 * p;
        int d  = idx >> 4;
        int q8 = (idx & 15) << 3;
        *(uint4*)&qs[d * QS2 + q8] =
            *(const uint4*)(qbase + (size_t)d * T_ + qt * 128 + q8);
    }

#define ATTN_CP_KV(kt0, st)                                                    \
    _Pragma("unroll") for (int p = 0; p < 2; p++) {                            \
        int idx = tid + 256 * p;                                               \
        int d  = idx >> 3;                                                     \
        int c8 = (idx & 7) << 3;                                               \
        cp16(ks_b + (st) * KVB + (d * KS2 + c8) * 2,                           \
             kbase + (size_t)d * T_ + (kt0) + c8);                             \
    }                                                                          \
    _Pragma("unroll") for (int p = 0; p < 4; p++) {                            \
        int idx = tid + 256 * p;                                               \
        int e  = idx >> 3;                                                     \
        int c8 = (idx & 7) << 3;                                               \
        cp16(vs_b + (st) * KVB + (e * KS2 + c8) * 2,                           \
             vbase + (size_t)e * T_ + (kt0) + c8);                             \
    }

    float o[16][4];
#pragma unroll
    for (int e = 0; e < 16; e++)
#pragma unroll
        for (int r = 0; r < 4; r++) o[e][r] = 0.f;
    float l_0 = 0.f, l_1 = 0.f;

    ATTN_CP_KV(0, 0);
    CP_COMMIT();

    for (int kt = 0; kt < 16; kt++) {
        if (kt + 1 < 16) { ATTN_CP_KV((kt + 1) * 64, (kt + 1) & 1); }
        CP_COMMIT();
        CP_WAIT1();
        __syncthreads();
        const unsigned stoff = (kt & 1) * KVB;

        float s[8][4];
#pragma unroll
        for (int ni = 0; ni < 8; ni++)
#pragma unroll
            for (int r = 0; r < 4; r++) s[ni][r] = 0.f;
#pragma unroll
        for (int kd = 0; kd < 4; kd++) {
            unsigned a[4];
            ldsm4t(a[0], a[1], a[2], a[3], qa0 + kd * 16 * QS2 * 2);
#pragma unroll
            for (int kvj = 0; kvj < 4; kvj++) {
                unsigned r0, r1, r2, r3;
                ldsm4t(r0, r1, r2, r3, ka0 + stoff + (kd * 16 * KS2 + kvj * 16) * 2);
                unsigned b0[2] = {r0, r1}, b1[2] = {r2, r3};
                mma_bf16(s[2 * kvj],     a, b0);
                mma_bf16(s[2 * kvj + 1], a, b1);
            }
        }

        unsigned pf[4][4];
#pragma unroll
        for (int j = 0; j < 4; j++) {
            float p00 = exp2f(s[2 * j][0]),     p01 = exp2f(s[2 * j][1]);
            float p02 = exp2f(s[2 * j][2]),     p03 = exp2f(s[2 * j][3]);
            float p10 = exp2f(s[2 * j + 1][0]), p11 = exp2f(s[2 * j + 1][1]);
            float p12 = exp2f(s[2 * j + 1][2]), p13 = exp2f(s[2 * j + 1][3]);
            l_0 += p00 + p01 + p10 + p11;
            l_1 += p02 + p03 + p12 + p13;
            pf[j][0] = packbf(p00, p01);
            pf[j][1] = packbf(p02, p03);
            pf[j][2] = packbf(p10, p11);
            pf[j][3] = packbf(p12, p13);
        }

#pragma unroll
        for (int j = 0; j < 4; j++) {
#pragma unroll
            for (int ej = 0; ej < 8; ej++) {
                unsigned r0, r1, r2, r3;
                ldsm4(r0, r1, r2, r3, va0 + stoff + (ej * 16 * KS2 + j * 16) * 2);
                unsigned b0[2] = {r0, r1}, b1[2] = {r2, r3};
                mma_bf16(o[2 * ej],     pf[j], b0);
                mma_bf16(o[2 * ej + 1], pf[j], b1);
            }
        }
        __syncthreads();
    }

    l_0 += __shfl_xor_sync(0xffffffffu, l_0, 1);
    l_0 += __shfl_xor_sync(0xffffffffu, l_0, 2);
    l_1 += __shfl_xor_sync(0xffffffffu, l_1, 1);
    l_1 += __shfl_xor_sync(0xffffffffu, l_1, 2);
    float inv0 = 1.f / l_0, inv1 = 1.f / l_1;
#pragma unroll
    for (int e = 0; e < 16; e++) {
        o[e][0] *= inv0; o[e][1] *= inv0;
        o[e][2] *= inv1; o[e][3] *= inv1;
    }

    // epilogue: two e-halves, transpose -> smem [e][t], fuse u-gating
    const __nv_bfloat16* ubase = g_u + (size_t)(b * E_ + h * EV_) * T_ + qt * 128;
    __nv_bfloat16* wbase = g_w + (size_t)(b * E_ + h * EV_) * T_ + qt * 128;
#pragma unroll
    for (int eh = 0; eh < 2; eh++) {
        __syncthreads();
#pragma unroll
        for (int et = eh * 8; et < eh * 8 + 8; et++) {
            int ec = et * 8 + 2 * th4 - eh * 64;
            os[ec * QS2 + wq + g]           = o[et][0];
            os[(ec + 1) * QS2 + wq + g]     = o[et][1];
            os[ec * QS2 + wq + g + 8]       = o[et][2];
            os[(ec + 1) * QS2 + wq + g + 8] = o[et][3];
        }
        __syncthreads();
#pragma unroll
        for (int p = 0; p < 4; p++) {
            int idx = tid + 256 * p;
            int e  = idx >> 4;
            int t8 = (idx & 15) << 3;
            int eg = eh * 64 + e;
            uint4 uv = *(const uint4*)(ubase + (size_t)eg * T_ + t8);
            const __nv_bfloat162* up = (const __nv_bfloat162*)&uv;
            const float* orow = os + e * QS2 + t8;
            float2 u0 = __bfloat1622float2(up[0]);
            float2 u1 = __bfloat1622float2(up[1]);
            float2 u2 = __bfloat1622float2(up[2]);
            float2 u3 = __bfloat1622float2(up[3]);
            uint4 wv = {
                packbf(u0.x * orow[0], u0.y * orow[1]),
                packbf(u1.x * orow[2], u1.y * orow[3]),
                packbf(u2.x * orow[4], u2.y * orow[5]),
                packbf(u3.x * orow[6], u3.y * orow[7])};
            *(uint4*)(wbase + (size_t)eg * T_ + t8) = wv;
        }
    }
}

// =============================================================================
// GEMM3: y = x + b_out + W_out @ w   M=512 K=1024 N=1024
// =============================================================================
__global__ __launch_bounds__(256) void gemm_out_bf16(
    const float* __restrict__ x, const float* __restrict__ bias)
{
    GEMM_DECL();
    const __nv_bfloat16* wb = g_w + (size_t)b * E_ * T_;
    GEMM_MAINLOOP(g_wo, E_, E_, wb);
    const float* xb = x + (size_t)b * C_ * T_;
    float* yp = g_y + (size_t)b * C_ * T_;
#pragma unroll
    for (int mi = 0; mi < 4; mi++) {
        int m = m0 + wm + mi * 16 + g;
        float bo0 = bias[m], bo1 = bias[m + 8];
#pragma unroll
        for (int ni = 0; ni < 8; ni++) {
            int n = n0 + wn + ni * 8 + 2 * th4;
            float2 x0 = *(const float2*)(xb + (size_t)m * T_ + n);
            float2 x1 = *(const float2*)(xb + (size_t)(m + 8) * T_ + n);
            float2 y0 = {acc[mi][ni][0] + bo0 + x0.x, acc[mi][ni][1] + bo0 + x0.y};
            float2 y1 = {acc[mi][ni][2] + bo1 + x1.x, acc[mi][ni][3] + bo1 + x1.y};
            *(float2*)(yp + (size_t)m * T_ + n)       = y0;
            *(float2*)(yp + (size_t)(m + 8) * T_ + n) = y1;
        }
    }
}

// =============================================================================
// RMSNorm over C
// =============================================================================
__global__ __launch_bounds__(256) void rms2_kernel(
    const float* __restrict__ gamma, float* __restrict__ out)
{
    __shared__ float red[8][32];
    __shared__ float rbuf[32];
    const int b = blockIdx.y;
    const int tseg = threadIdx.x & 31, cseg = threadIdx.x >> 5;
    const int t = blockIdx.x * 32 + tseg;
    const float* yb = g_y + (size_t)b * C_ * T_ + t;
    float ss = 0.f;
#pragma unroll 8
    for (int c = cseg * 64; c < cseg * 64 + 64; c++) {
        float v = yb[(size_t)c * T_];
        ss += v * v;
    }
    red[cseg][tseg] = ss;
    __syncthreads();
    if (cseg == 0) {
        float tot = 0.f;
#pragma unroll
        for (int i = 0; i < 8; i++) tot += red[i][tseg];
        rbuf[tseg] = rsqrtf(tot * (1.f / C_) + 1e-5f);
    }
    __syncthreads();
    float r = rbuf[tseg];
    float* op = out + (size_t)b * C_ * T_ + t;
#pragma unroll 8
    for (int c = cseg * 64; c < cseg * 64 + 64; c++) {
        op[(size_t)c * T_] = yb[(size_t)c * T_] * r * gamma[c];
    }
}

// =============================================================================
// launch
// =============================================================================
extern "C" void kernel_launch(void* const* d_in, const int* in_sizes, int n_in,
                              void* d_out, int out_size)
{
    const float* x      = (const float*)d_in[0];
    const float* W_in   = (const float*)d_in[1];
    const float* b_in   = (const float*)d_in[2];
    const float* W_attn = (const float*)d_in[3];
    const float* b_attn = (const float*)d_in[4];
    const float* w_q    = (const float*)d_in[5];
    const float* b_q    = (const float*)d_in[6];
    const float* w_k    = (const float*)d_in[7];
    const float* b_k    = (const float*)d_in[8];
    const float* W_out  = (const float*)d_in[9];
    const float* b_out  = (const float*)d_in[10];
    const float* gamma  = (const float*)d_in[11];
    float* out = (float*)d_out;

    cudaFuncSetAttribute(gemm_uv_bf16,
                         cudaFuncAttributeMaxDynamicSharedMemorySize, GEMM_SMEM);
    cudaFuncSetAttribute(gemm_qk_bf16,
                         cudaFuncAttributeMaxDynamicSharedMemorySize, GEMM_SMEM);
    cudaFuncSetAttribute(gemm_out_bf16,
                         cudaFuncAttributeMaxDynamicSharedMemorySize, GEMM_SMEM);
    cudaFuncSetAttribute(attn_bf16_kernel,
                         cudaFuncAttributeMaxDynamicSharedMemorySize, ATTN_SMEM);

    conv_all<<<CV3, 256>>>(W_in, W_attn, W_out, x);

    gemm_uv_bf16<<<dim3(T_ / 256, 2 * E_ / 128, B_), 256, GEMM_SMEM>>>(b_in);
    gemm_qk_bf16<<<dim3(T_ / 256, QK_ / 128, B_), 256, GEMM_SMEM>>>(b_attn, w_q, b_q, w_k, b_k);
    attn_bf16_kernel<<<dim3(T_ / 128, H_, B_), 256, ATTN_SMEM>>>();
    gemm_out_bf16<<<dim3(T_ / 256, C_ / 128, B_), 256, GEMM_SMEM>>>(x, b_out);
    rms2_kernel<<<dim3(T_ / 32, B_), 256>>>(gamma, out);
}

// round 13
// speedup vs baseline: 1.1841x; 1.1841x over previous
#include <cuda_runtime.h>
#include <cuda_bf16.h>
#include <math.h>

#define B_  8
#define C_  512
#define T_  1024
#define E_  1024
#define H_  8
#define HD_ 64
#define QK_ 512
#define EV_ 128

// log(1024)/log(512)/sqrt(64) * log2(e)  (exp2-based softmax)
#define QSCALE_ 0.20037157933881626f

// ---------------- scratch (bf16 intermediates) ----------------
static __device__ __nv_bfloat16 g_u[(size_t)B_ * E_ * T_];
static __device__ __nv_bfloat16 g_v[(size_t)B_ * E_ * T_];
static __device__ __nv_bfloat16 g_q[(size_t)B_ * QK_ * T_];   // pre-scaled
static __device__ __nv_bfloat16 g_k[(size_t)B_ * QK_ * T_];
static __device__ __nv_bfloat16 g_w[(size_t)B_ * E_ * T_];
static __device__ float g_y[(size_t)B_ * C_ * T_];
static __device__ __nv_bfloat16 g_wi[(size_t)2 * E_ * C_];
static __device__ __nv_bfloat16 g_wa[(size_t)QK_ * C_];
static __device__ __nv_bfloat16 g_wo[(size_t)C_ * E_];
static __device__ __nv_bfloat16 g_xb[(size_t)B_ * C_ * T_];

// ---------------- helpers ----------------
__device__ __forceinline__ unsigned packbf(float lo, float hi) {
    unsigned r;
    asm("cvt.rn.bf16x2.f32 %0, %1, %2;" : "=r"(r) : "f"(hi), "f"(lo));
    return r;
}
__device__ __forceinline__ void mma_bf16(float* d, const unsigned* a, const unsigned* b) {
    asm volatile(
        "mma.sync.aligned.m16n8k16.row.col.f32.bf16.bf16.f32 "
        "{%0,%1,%2,%3}, {%4,%5,%6,%7}, {%8,%9}, {%0,%1,%2,%3};"
        : "+f"(d[0]), "+f"(d[1]), "+f"(d[2]), "+f"(d[3])
        : "r"(a[0]), "r"(a[1]), "r"(a[2]), "r"(a[3]), "r"(b[0]), "r"(b[1]));
}
__device__ __forceinline__ void ldsm4(unsigned& r0, unsigned& r1, unsigned& r2, unsigned& r3,
                                      unsigned addr) {
    asm volatile("ldmatrix.sync.aligned.m8n8.x4.shared.b16 {%0,%1,%2,%3}, [%4];"
                 : "=r"(r0), "=r"(r1), "=r"(r2), "=r"(r3) : "r"(addr));
}
__device__ __forceinline__ void ldsm4t(unsigned& r0, unsigned& r1, unsigned& r2, unsigned& r3,
                                       unsigned addr) {
    asm volatile("ldmatrix.sync.aligned.m8n8.x4.trans.shared.b16 {%0,%1,%2,%3}, [%4];"
                 : "=r"(r0), "=r"(r1), "=r"(r2), "=r"(r3) : "r"(addr));
}
__device__ __forceinline__ void cp16(unsigned saddr, const void* gptr) {
    asm volatile("cp.async.cg.shared.global [%0], [%1], 16;"
                 :: "r"(saddr), "l"(gptr));
}
#define CP_COMMIT() asm volatile("cp.async.commit_group;" ::: "memory")
#define CP_WAIT1()  asm volatile("cp.async.wait_group 1;" ::: "memory")
#define CP_WAIT2()  asm volatile("cp.async.wait_group 2;" ::: "memory")

// ---------------- fused fp32 -> bf16 conversion (all 4 tensors, 1 launch) ----
#define CV0 512
#define CV1 (CV0 + 128)
#define CV2 (CV1 + 256)
#define CV3 (CV2 + 2048)
__global__ __launch_bounds__(256) void conv_all(
    const float* __restrict__ s0, const float* __restrict__ s1,
    const float* __restrict__ s2, const float* __restrict__ s3)
{
    int blk = blockIdx.x;
    const float* src;
    __nv_bfloat16* dst;
    int rel;
    if      (blk < CV0) { src = s0; dst = g_wi; rel = blk; }
    else if (blk < CV1) { src = s1; dst = g_wa; rel = blk - CV0; }
    else if (blk < CV2) { src = s2; dst = g_wo; rel = blk - CV1; }
    else                { src = s3; dst = g_xb; rel = blk - CV2; }
    size_t i = ((size_t)rel * 256 + threadIdx.x) * 8;
    float4 a = *(const float4*)(src + i);
    float4 b = *(const float4*)(src + i + 4);
    uint4 w = {packbf(a.x, a.y), packbf(a.z, a.w), packbf(b.x, b.y), packbf(b.z, b.w)};
    *(uint4*)(dst + i) = w;
}

// ---------------- GEMM: 128x128 CTA, BK=32, 4-stage cp.async (R8 shape) ------
#define ASTR 40
#define BSTR 136
#define ASZ (128 * ASTR)
#define BSZ (32 * BSTR)
#define GST 4
#define GEMM_SMEM ((GST * (ASZ + BSZ)) * 2)   // 75776 bytes; 2 CTAs fit/SM

#define GEMM_DECL()                                                            \
    extern __shared__ __align__(16) unsigned short gsm[];                      \
    unsigned short* As = gsm;                                                  \
    unsigned short* Bs = gsm + GST * ASZ;                                      \
    const int b   = blockIdx.z;                                                \
    const int m0  = blockIdx.y * 128;                                          \
    const int n0  = blockIdx.x * 128;                                          \
    const int tid = threadIdx.x;                                               \
    const int lane = tid & 31, warp = tid >> 5;                                \
    const int g = lane >> 2, th4 = lane & 3;                                   \
    const int wm = (warp & 1) * 64, wn = (warp >> 1) * 32;                     \
    const unsigned as_b = (unsigned)__cvta_generic_to_shared(As);              \
    const unsigned bs_b = (unsigned)__cvta_generic_to_shared(Bs);              \
    const unsigned a_addr0 = as_b + ((wm + (lane & 15)) * ASTR + (lane >> 4) * 8) * 2; \
    const unsigned b_addr0 = bs_b + ((lane & 15) * BSTR + wn + (lane >> 4) * 8) * 2;   \
    float acc[4][4][4];                                                        \
    _Pragma("unroll") for (int i = 0; i < 4; i++)                              \
    _Pragma("unroll") for (int j = 0; j < 4; j++)                              \
    _Pragma("unroll") for (int r = 0; r < 4; r++) acc[i][j][r] = 0.f;

#define GEMM_CP(Wb, ldk, Xb, k0, st)                                           \
    _Pragma("unroll") for (int p = 0; p < 2; p++) {                            \
        int idx = tid + 256 * p;                                               \
        cp16(as_b + (st) * ASZ * 2 + ((idx >> 2) * ASTR + (idx & 3) * 8) * 2,  \
             (Wb) + (size_t)(m0 + (idx >> 2)) * (ldk) + (k0) + (idx & 3) * 8); \
        cp16(bs_b + (st) * BSZ * 2 + ((idx >> 4) * BSTR + (idx & 15) * 8) * 2, \
             (Xb) + (size_t)((k0) + (idx >> 4)) * T_ + n0 + (idx & 15) * 8);   \
    }

#define GEMM_COMPUTE(st)                                                       \
    _Pragma("unroll") for (int ks16 = 0; ks16 < 2; ks16++) {                   \
        unsigned af[4][4], bf[4][2];                                           \
        _Pragma("unroll") for (int mi = 0; mi < 4; mi++)                       \
            ldsm4(af[mi][0], af[mi][1], af[mi][2], af[mi][3],                  \
                  a_addr0 + (st) * ASZ * 2 + (mi * 16 * ASTR + ks16 * 16) * 2);\
        _Pragma("unroll") for (int nj = 0; nj < 2; nj++)                       \
            ldsm4t(bf[nj*2][0], bf[nj*2][1], bf[nj*2+1][0], bf[nj*2+1][1],     \
                   b_addr0 + (st) * BSZ * 2 + (ks16 * 16 * BSTR + nj * 16) * 2);\
        _Pragma("unroll") for (int mi = 0; mi < 4; mi++)                       \
        _Pragma("unroll") for (int ni = 0; ni < 4; ni++)                       \
            mma_bf16(acc[mi][ni], af[mi], bf[ni]);                             \
    }

#define GEMM_MAINLOOP(Wb, ldk, KK, Xb)                                         \
    {                                                                          \
        const int nit = (KK) / 32;                                             \
        GEMM_CP(Wb, ldk, Xb, 0, 0);  CP_COMMIT();                              \
        GEMM_CP(Wb, ldk, Xb, 32, 1); CP_COMMIT();                              \
        GEMM_CP(Wb, ldk, Xb, 64, 2); CP_COMMIT();                              \
        for (int it = 0; it < nit; it++) {                                     \
            CP_WAIT2();                                                        \
            __syncthreads();                                                   \
            if (it + 3 < nit) { GEMM_CP(Wb, ldk, Xb, (it + 3) * 32, (it + 3) & 3); } \
            CP_COMMIT();                                                       \
            GEMM_COMPUTE(it & 3);                                              \
        }                                                                      \
    }

// =============================================================================
// Merged GEMM1+GEMM2: grid.y 0..15 -> u/v (W_in, silu); 16..19 -> q/k (W_attn)
// Both share B = xb, K = 512. One launch = better wave packing.
// =============================================================================
__global__ __launch_bounds__(256, 2) void gemm_uvqk_bf16(
    const float* __restrict__ b_in,
    const float* __restrict__ b_attn,
    const float* __restrict__ wq, const float* __restrict__ bq,
    const float* __restrict__ wk, const float* __restrict__ bk)
{
    GEMM_DECL();
    const __nv_bfloat16* xb = g_xb + (size_t)b * C_ * T_;
    const __nv_bfloat16* Ap = (m0 < 2 * E_)
        ? g_wi
        : g_wa - (size_t)(2 * E_) * C_;   // index with m0 directly
    GEMM_MAINLOOP(Ap, C_, C_, xb);

    if (m0 < 2 * E_) {
        // ---- u/v epilogue: silu ----
        __nv_bfloat16* outp = (m0 < E_)
            ? g_u + (size_t)b * E_ * T_
            : g_v + (size_t)b * E_ * T_ - (size_t)E_ * T_;
#pragma unroll
        for (int mi = 0; mi < 4; mi++) {
            int m = m0 + wm + mi * 16 + g;
            float b0 = b_in[m], b1 = b_in[m + 8];
#pragma unroll
            for (int ni = 0; ni < 4; ni++) {
                int n = n0 + wn + ni * 8 + 2 * th4;
                float t0 = acc[mi][ni][0] + b0, t1 = acc[mi][ni][1] + b0;
                float t2 = acc[mi][ni][2] + b1, t3 = acc[mi][ni][3] + b1;
                unsigned w0 = packbf(t0 / (1.f + __expf(-t0)), t1 / (1.f + __expf(-t1)));
                unsigned w1 = packbf(t2 / (1.f + __expf(-t2)), t3 / (1.f + __expf(-t3)));
                *(unsigned*)(outp + (size_t)m * T_ + n)       = w0;
                *(unsigned*)(outp + (size_t)(m + 8) * T_ + n) = w1;
            }
        }
    } else {
        // ---- q/k epilogue ----
        const int mq0 = m0 - 2 * E_;
        __nv_bfloat16* qp = g_q + (size_t)b * QK_ * T_;
        __nv_bfloat16* kp = g_k + (size_t)b * QK_ * T_;
#pragma unroll
        for (int mi = 0; mi < 4; mi++) {
            int m = mq0 + wm + mi * 16 + g;
            float bi0 = b_attn[m], bi1 = b_attn[m + 8];
            float wq0 = wq[m] * QSCALE_, bq0 = bq[m] * QSCALE_;
            float wk0 = wk[m], bk0 = bk[m];
            float wq1 = wq[m + 8] * QSCALE_, bq1 = bq[m + 8] * QSCALE_;
            float wk1 = wk[m + 8], bk1 = bk[m + 8];
#pragma unroll
            for (int ni = 0; ni < 4; ni++) {
                int n = n0 + wn + ni * 8 + 2 * th4;
                float z0 = acc[mi][ni][0] + bi0, z1 = acc[mi][ni][1] + bi0;
                float z2 = acc[mi][ni][2] + bi1, z3 = acc[mi][ni][3] + bi1;
                *(unsigned*)(qp + (size_t)m * T_ + n)       = packbf(z0 * wq0 + bq0, z1 * wq0 + bq0);
                *(unsigned*)(qp + (size_t)(m + 8) * T_ + n) = packbf(z2 * wq1 + bq1, z3 * wq1 + bq1);
                *(unsigned*)(kp + (size_t)m * T_ + n)       = packbf(z0 * wk0 + bk0, z1 * wk0 + bk0);
                *(unsigned*)(kp + (size_t)(m + 8) * T_ + n) = packbf(z2 * wk1 + bk1, z3 * wk1 + bk1);
            }
        }
    }
}

// =============================================================================
// Flash attention bf16, BQ=128 (8 warps x 16 rows), BKV=64,
// 2-stage cp.async KV pipeline, no-max exp2 softmax, fused u-gating epilogue.
// __launch_bounds__(256,2): regs<=128 so 2 CTAs/SM. (R10 structure, unchanged.)
// =============================================================================
#define QS2 136
#define KS2 72
#define KVB (192 * KS2 * 2)
#define QS_BYTES (64 * QS2 * 2)
#define ATTN_SMEM (QS_BYTES + 2 * KVB)

__global__ __launch_bounds__(256, 2) void attn_bf16_kernel()
{
    extern __shared__ __align__(16) char dsm[];
    unsigned short* qs = (unsigned short*)dsm;
    unsigned short* ks = (unsigned short*)(dsm + QS_BYTES);
    unsigned short* vs = ks + 64 * KS2;
    float* os = (float*)(dsm + QS_BYTES);   // epilogue alias

    const int b  = blockIdx.z;
    const int h  = blockIdx.y;
    const int qt = blockIdx.x;
    const int tid = threadIdx.x;
    const int lane = tid & 31, warp = tid >> 5;
    const int g = lane >> 2, th4 = lane & 3;
    const int wq = warp * 16;

    const __nv_bfloat16* qbase = g_q + (size_t)(b * QK_ + h * HD_) * T_;
    const __nv_bfloat16* kbase = g_k + (size_t)(b * QK_ + h * HD_) * T_;
    const __nv_bfloat16* vbase = g_v + (size_t)(b * E_ + h * EV_) * T_;

    const unsigned qs_b = (unsigned)__cvta_generic_to_shared(qs);
    const unsigned ks_b = (unsigned)__cvta_generic_to_shared(ks);
    const unsigned vs_b = (unsigned)__cvta_generic_to_shared(vs);

    const unsigned qa0 = qs_b + ((((lane >> 4) << 3) + (lane & 7)) * QS2 + wq + (lane & 8)) * 2;
    const unsigned ka0 = ks_b + (((lane & 7) + ((lane >> 3) & 1) * 8) * KS2 + ((lane >> 4) & 1) * 8) * 2;
    const unsigned va0 = vs_b + (((lane & 7) + ((lane >> 4) & 1) * 8) * KS2 + (lane & 8)) * 2;

#pragma unroll
    for (int p = 0; p < 4; p++) {
        int idx = tid + 256 * p;
        int d  = idx >> 4;
        int q8 = (idx & 15) << 3;
        *(uint4*)&qs[d * QS2 + q8] =
            *(const uint4*)(qbase + (size_t)d * T_ + qt * 128 + q8);
    }

#define ATTN_CP_KV(kt0, st)                                                    \
    _Pragma("unroll") for (int p = 0; p < 2; p++) {                            \
        int idx = tid + 256 * p;                                               \
        int d  = idx >> 3;                                                     \
        int c8 = (idx & 7) << 3;                                               \
        cp16(ks_b + (st) * KVB + (d * KS2 + c8) * 2,                           \
             kbase + (size_t)d * T_ + (kt0) + c8);                             \
    }                                                                          \
    _Pragma("unroll") for (int p = 0; p < 4; p++) {                            \
        int idx = tid + 256 * p;                                               \
        int e  = idx >> 3;                                                     \
        int c8 = (idx & 7) << 3;                                               \
        cp16(vs_b + (st) * KVB + (e * KS2 + c8) * 2,                           \
             vbase + (size_t)e * T_ + (kt0) + c8);                             \
    }

    float o[16][4];
#pragma unroll
    for (int e = 0; e < 16; e++)
#pragma unroll
        for (int r = 0; r < 4; r++) o[e][r] = 0.f;
    float l_0 = 0.f, l_1 = 0.f;

    ATTN_CP_KV(0, 0);
    CP_COMMIT();

    for (int kt = 0; kt < 16; kt++) {
        if (kt + 1 < 16) { ATTN_CP_KV((kt + 1) * 64, (kt + 1) & 1); }
        CP_COMMIT();
        CP_WAIT1();
        __syncthreads();
        const unsigned stoff = (kt & 1) * KVB;

        float s[8][4];
#pragma unroll
        for (int ni = 0; ni < 8; ni++)
#pragma unroll
            for (int r = 0; r < 4; r++) s[ni][r] = 0.f;
#pragma unroll
        for (int kd = 0; kd < 4; kd++) {
            unsigned a[4];
            ldsm4t(a[0], a[1], a[2], a[3], qa0 + kd * 16 * QS2 * 2);
#pragma unroll
            for (int kvj = 0; kvj < 4; kvj++) {
                unsigned r0, r1, r2, r3;
                ldsm4t(r0, r1, r2, r3, ka0 + stoff + (kd * 16 * KS2 + kvj * 16) * 2);
                unsigned b0[2] = {r0, r1}, b1[2] = {r2, r3};
                mma_bf16(s[2 * kvj],     a, b0);
                mma_bf16(s[2 * kvj + 1], a, b1);
            }
        }

        unsigned pf[4][4];
#pragma unroll
        for (int j = 0; j < 4; j++) {
            float p00 = exp2f(s[2 * j][0]),     p01 = exp2f(s[2 * j][1]);
            float p02 = exp2f(s[2 * j][2]),     p03 = exp2f(s[2 * j][3]);
            float p10 = exp2f(s[2 * j + 1][0]), p11 = exp2f(s[2 * j + 1][1]);
            float p12 = exp2f(s[2 * j + 1][2]), p13 = exp2f(s[2 * j + 1][3]);
            l_0 += p00 + p01 + p10 + p11;
            l_1 += p02 + p03 + p12 + p13;
            pf[j][0] = packbf(p00, p01);
            pf[j][1] = packbf(p02, p03);
            pf[j][2] = packbf(p10, p11);
            pf[j][3] = packbf(p12, p13);
        }

#pragma unroll
        for (int j = 0; j < 4; j++) {
#pragma unroll
            for (int ej = 0; ej < 8; ej++) {
                unsigned r0, r1, r2, r3;
                ldsm4(r0, r1, r2, r3, va0 + stoff + (ej * 16 * KS2 + j * 16) * 2);
                unsigned b0[2] = {r0, r1}, b1[2] = {r2, r3};
                mma_bf16(o[2 * ej],     pf[j], b0);
                mma_bf16(o[2 * ej + 1], pf[j], b1);
            }
        }
        __syncthreads();
    }

    l_0 += __shfl_xor_sync(0xffffffffu, l_0, 1);
    l_0 += __shfl_xor_sync(0xffffffffu, l_0, 2);
    l_1 += __shfl_xor_sync(0xffffffffu, l_1, 1);
    l_1 += __shfl_xor_sync(0xffffffffu, l_1, 2);
    float inv0 = 1.f / l_0, inv1 = 1.f / l_1;
#pragma unroll
    for (int e = 0; e < 16; e++) {
        o[e][0] *= inv0; o[e][1] *= inv0;
        o[e][2] *= inv1; o[e][3] *= inv1;
    }

    // epilogue: two e-halves, transpose -> smem [e][t], fuse u-gating
    const __nv_bfloat16* ubase = g_u + (size_t)(b * E_ + h * EV_) * T_ + qt * 128;
    __nv_bfloat16* wbase = g_w + (size_t)(b * E_ + h * EV_) * T_ + qt * 128;
#pragma unroll
    for (int eh = 0; eh < 2; eh++) {
        __syncthreads();
#pragma unroll
        for (int et = eh * 8; et < eh * 8 + 8; et++) {
            int ec = et * 8 + 2 * th4 - eh * 64;
            os[ec * QS2 + wq + g]           = o[et][0];
            os[(ec + 1) * QS2 + wq + g]     = o[et][1];
            os[ec * QS2 + wq + g + 8]       = o[et][2];
            os[(ec + 1) * QS2 + wq + g + 8] = o[et][3];
        }
        __syncthreads();
#pragma unroll
        for (int p = 0; p < 4; p++) {
            int idx = tid + 256 * p;
            int e  = idx >> 4;
            int t8 = (idx & 15) << 3;
            int eg = eh * 64 + e;
            uint4 uv = *(const uint4*)(ubase + (size_t)eg * T_ + t8);
            const __nv_bfloat162* up = (const __nv_bfloat162*)&uv;
            const float* orow = os + e * QS2 + t8;
            float2 u0 = __bfloat1622float2(up[0]);
            float2 u1 = __bfloat1622float2(up[1]);
            float2 u2 = __bfloat1622float2(up[2]);
            float2 u3 = __bfloat1622float2(up[3]);
            uint4 wv = {
                packbf(u0.x * orow[0], u0.y * orow[1]),
                packbf(u1.x * orow[2], u1.y * orow[3]),
                packbf(u2.x * orow[4], u2.y * orow[5]),
                packbf(u3.x * orow[6], u3.y * orow[7])};
            *(uint4*)(wbase + (size_t)eg * T_ + t8) = wv;
        }
    }
}

// =============================================================================
// GEMM3: y = x + b_out + W_out @ w   M=512 K=1024 N=1024
// =============================================================================
__global__ __launch_bounds__(256, 2) void gemm_out_bf16(
    const float* __restrict__ x, const float* __restrict__ bias)
{
    GEMM_DECL();
    const __nv_bfloat16* wb = g_w + (size_t)b * E_ * T_;
    GEMM_MAINLOOP(g_wo, E_, E_, wb);
    const float* xb = x + (size_t)b * C_ * T_;
    float* yp = g_y + (size_t)b * C_ * T_;
#pragma unroll
    for (int mi = 0; mi < 4; mi++) {
        int m = m0 + wm + mi * 16 + g;
        float bo0 = bias[m], bo1 = bias[m + 8];
#pragma unroll
        for (int ni = 0; ni < 4; ni++) {
            int n = n0 + wn + ni * 8 + 2 * th4;
            float2 x0 = *(const float2*)(xb + (size_t)m * T_ + n);
            float2 x1 = *(const float2*)(xb + (size_t)(m + 8) * T_ + n);
            float2 y0 = {acc[mi][ni][0] + bo0 + x0.x, acc[mi][ni][1] + bo0 + x0.y};
            float2 y1 = {acc[mi][ni][2] + bo1 + x1.x, acc[mi][ni][3] + bo1 + x1.y};
            *(float2*)(yp + (size_t)m * T_ + n)       = y0;
            *(float2*)(yp + (size_t)(m + 8) * T_ + n) = y1;
        }
    }
}

// =============================================================================
// RMSNorm over C
// =============================================================================
__global__ __launch_bounds__(256) void rms2_kernel(
    const float* __restrict__ gamma, float* __restrict__ out)
{
    __shared__ float red[8][32];
    __shared__ float rbuf[32];
    const int b = blockIdx.y;
    const int tseg = threadIdx.x & 31, cseg = threadIdx.x >> 5;
    const int t = blockIdx.x * 32 + tseg;
    const float* yb = g_y + (size_t)b * C_ * T_ + t;
    float ss = 0.f;
#pragma unroll 8
    for (int c = cseg * 64; c < cseg * 64 + 64; c++) {
        float v = yb[(size_t)c * T_];
        ss += v * v;
    }
    red[cseg][tseg] = ss;
    __syncthreads();
    if (cseg == 0) {
        float tot = 0.f;
#pragma unroll
        for (int i = 0; i < 8; i++) tot += red[i][tseg];
        rbuf[tseg] = rsqrtf(tot * (1.f / C_) + 1e-5f);
    }
    __syncthreads();
    float r = rbuf[tseg];
    float* op = out + (size_t)b * C_ * T_ + t;
#pragma unroll 8
    for (int c = cseg * 64; c < cseg * 64 + 64; c++) {
        op[(size_t)c * T_] = yb[(size_t)c * T_] * r * gamma[c];
    }
}

// =============================================================================
// launch
// =============================================================================
extern "C" void kernel_launch(void* const* d_in, const int* in_sizes, int n_in,
                              void* d_out, int out_size)
{
    const float* x      = (const float*)d_in[0];
    const float* W_in   = (const float*)d_in[1];
    const float* b_in   = (const float*)d_in[2];
    const float* W_attn = (const float*)d_in[3];
    const float* b_attn = (const float*)d_in[4];
    const float* w_q    = (const float*)d_in[5];
    const float* b_q    = (const float*)d_in[6];
    const float* w_k    = (const float*)d_in[7];
    const float* b_k    = (const float*)d_in[8];
    const float* W_out  = (const float*)d_in[9];
    const float* b_out  = (const float*)d_in[10];
    const float* gamma  = (const float*)d_in[11];
    float* out = (float*)d_out;

    cudaFuncSetAttribute(gemm_uvqk_bf16,
                         cudaFuncAttributeMaxDynamicSharedMemorySize, GEMM_SMEM);
    cudaFuncSetAttribute(gemm_out_bf16,
                         cudaFuncAttributeMaxDynamicSharedMemorySize, GEMM_SMEM);
    cudaFuncSetAttribute(attn_bf16_kernel,
                         cudaFuncAttributeMaxDynamicSharedMemorySize, ATTN_SMEM);

    conv_all<<<CV3, 256>>>(W_in, W_attn, W_out, x);

    // merged u/v (rows 0..2047) + q/k (rows 2048..2559): grid.y = 20 tiles
    gemm_uvqk_bf16<<<dim3(T_ / 128, 20, B_), 256, GEMM_SMEM>>>(
        b_in, b_attn, w_q, b_q, w_k, b_k);
    attn_bf16_kernel<<<dim3(T_ / 128, H_, B_), 256, ATTN_SMEM>>>();
    gemm_out_bf16<<<dim3(T_ / 128, C_ / 128, B_), 256, GEMM_SMEM>>>(x, b_out);
    rms2_kernel<<<dim3(T_ / 32, B_), 256>>>(gamma, out);
}

// round 14
// speedup vs baseline: 1.2067x; 1.0191x over previous
#include <cuda_runtime.h>
#include <cuda_bf16.h>
#include <math.h>

#define B_  8
#define C_  512
#define T_  1024
#define E_  1024
#define H_  8
#define HD_ 64
#define QK_ 512
#define EV_ 128

// log(1024)/log(512)/sqrt(64) * log2(e)  (exp2-based softmax)
#define QSCALE_ 0.20037157933881626f

// ---------------- scratch (bf16 intermediates) ----------------
static __device__ __nv_bfloat16 g_u[(size_t)B_ * E_ * T_];
static __device__ __nv_bfloat16 g_v[(size_t)B_ * E_ * T_];
static __device__ __nv_bfloat16 g_q[(size_t)B_ * QK_ * T_];   // pre-scaled
static __device__ __nv_bfloat16 g_k[(size_t)B_ * QK_ * T_];
static __device__ __nv_bfloat16 g_w[(size_t)B_ * E_ * T_];
static __device__ float g_y[(size_t)B_ * C_ * T_];
static __device__ __nv_bfloat16 g_wi[(size_t)2 * E_ * C_];
static __device__ __nv_bfloat16 g_wa[(size_t)QK_ * C_];
static __device__ __nv_bfloat16 g_wo[(size_t)C_ * E_];
static __device__ __nv_bfloat16 g_xb[(size_t)B_ * C_ * T_];

// ---------------- helpers ----------------
__device__ __forceinline__ unsigned packbf(float lo, float hi) {
    unsigned r;
    asm("cvt.rn.bf16x2.f32 %0, %1, %2;" : "=r"(r) : "f"(hi), "f"(lo));
    return r;
}
__device__ __forceinline__ void mma_bf16(float* d, const unsigned* a, const unsigned* b) {
    asm volatile(
        "mma.sync.aligned.m16n8k16.row.col.f32.bf16.bf16.f32 "
        "{%0,%1,%2,%3}, {%4,%5,%6,%7}, {%8,%9}, {%0,%1,%2,%3};"
        : "+f"(d[0]), "+f"(d[1]), "+f"(d[2]), "+f"(d[3])
        : "r"(a[0]), "r"(a[1]), "r"(a[2]), "r"(a[3]), "r"(b[0]), "r"(b[1]));
}
__device__ __forceinline__ void ldsm4(unsigned& r0, unsigned& r1, unsigned& r2, unsigned& r3,
                                      unsigned addr) {
    asm volatile("ldmatrix.sync.aligned.m8n8.x4.shared.b16 {%0,%1,%2,%3}, [%4];"
                 : "=r"(r0), "=r"(r1), "=r"(r2), "=r"(r3) : "r"(addr));
}
__device__ __forceinline__ void ldsm4t(unsigned& r0, unsigned& r1, unsigned& r2, unsigned& r3,
                                       unsigned addr) {
    asm volatile("ldmatrix.sync.aligned.m8n8.x4.trans.shared.b16 {%0,%1,%2,%3}, [%4];"
                 : "=r"(r0), "=r"(r1), "=r"(r2), "=r"(r3) : "r"(addr));
}
__device__ __forceinline__ void cp16(unsigned saddr, const void* gptr) {
    asm volatile("cp.async.cg.shared.global [%0], [%1], 16;"
                 :: "r"(saddr), "l"(gptr));
}
#define CP_COMMIT() asm volatile("cp.async.commit_group;" ::: "memory")
#define CP_WAIT1()  asm volatile("cp.async.wait_group 1;" ::: "memory")

// ---------------- fused fp32 -> bf16 conversion (all 4 tensors, 1 launch) ----
#define CV0 512
#define CV1 (CV0 + 128)
#define CV2 (CV1 + 256)
#define CV3 (CV2 + 2048)
__global__ __launch_bounds__(256) void conv_all(
    const float* __restrict__ s0, const float* __restrict__ s1,
    const float* __restrict__ s2, const float* __restrict__ s3)
{
    int blk = blockIdx.x;
    const float* src;
    __nv_bfloat16* dst;
    int rel;
    if      (blk < CV0) { src = s0; dst = g_wi; rel = blk; }
    else if (blk < CV1) { src = s1; dst = g_wa; rel = blk - CV0; }
    else if (blk < CV2) { src = s2; dst = g_wo; rel = blk - CV1; }
    else                { src = s3; dst = g_xb; rel = blk - CV2; }
    size_t i = ((size_t)rel * 256 + threadIdx.x) * 8;
    float4 a = *(const float4*)(src + i);
    float4 b = *(const float4*)(src + i + 4);
    uint4 w = {packbf(a.x, a.y), packbf(a.z, a.w), packbf(b.x, b.y), packbf(b.z, b.w)};
    *(uint4*)(dst + i) = w;
}

// ------- GEMM: 128x128 CTA, BK=64, 3-stage cp.async, ONE barrier per iter ----
#define ASTR 72                       // 64 + 8 pad (conflict-free ldsm)
#define BSTR 136
#define ASZ (128 * ASTR)              // 9216 ush per A stage
#define BSZ (64 * BSTR)               // 8704 ush per B stage
#define GST 3
#define GEMM_SMEM ((GST * (ASZ + BSZ)) * 2)   // 107520 B; 2 CTAs = 215040 <= 228KB

#define GEMM_DECL()                                                            \
    extern __shared__ __align__(16) unsigned short gsm[];                      \
    unsigned short* As = gsm;                                                  \
    unsigned short* Bs = gsm + GST * ASZ;                                      \
    const int b   = blockIdx.z;                                                \
    const int m0  = blockIdx.y * 128;                                          \
    const int n0  = blockIdx.x * 128;                                          \
    const int tid = threadIdx.x;                                               \
    const int lane = tid & 31, warp = tid >> 5;                                \
    const int g = lane >> 2, th4 = lane & 3;                                   \
    const int wm = (warp & 1) * 64, wn = (warp >> 1) * 32;                     \
    const unsigned as_b = (unsigned)__cvta_generic_to_shared(As);              \
    const unsigned bs_b = (unsigned)__cvta_generic_to_shared(Bs);              \
    const unsigned a_addr0 = as_b + ((wm + (lane & 15)) * ASTR + (lane >> 4) * 8) * 2; \
    const unsigned b_addr0 = bs_b + ((lane & 15) * BSTR + wn + (lane >> 4) * 8) * 2;   \
    float acc[4][4][4];                                                        \
    _Pragma("unroll") for (int i = 0; i < 4; i++)                              \
    _Pragma("unroll") for (int j = 0; j < 4; j++)                              \
    _Pragma("unroll") for (int r = 0; r < 4; r++) acc[i][j][r] = 0.f;

// A: 128 rows x 64 cols = 1024 cp16; B: 64 rows x 128 cols = 1024 cp16
#define GEMM_CP(Wb, ldk, Xb, k0, st)                                           \
    _Pragma("unroll") for (int p = 0; p < 4; p++) {                            \
        int idx = tid + 256 * p;                                               \
        cp16(as_b + (st) * ASZ * 2 + ((idx >> 3) * ASTR + (idx & 7) * 8) * 2,  \
             (Wb) + (size_t)(m0 + (idx >> 3)) * (ldk) + (k0) + (idx & 7) * 8); \
        cp16(bs_b + (st) * BSZ * 2 + ((idx >> 4) * BSTR + (idx & 15) * 8) * 2, \
             (Xb) + (size_t)((k0) + (idx >> 4)) * T_ + n0 + (idx & 15) * 8);   \
    }

#define GEMM_COMPUTE(st)                                                       \
    _Pragma("unroll") for (int ks16 = 0; ks16 < 4; ks16++) {                   \
        unsigned af[4][4], bf[4][2];                                           \
        _Pragma("unroll") for (int mi = 0; mi < 4; mi++)                       \
            ldsm4(af[mi][0], af[mi][1], af[mi][2], af[mi][3],                  \
                  a_addr0 + (st) * ASZ * 2 + (mi * 16 * ASTR + ks16 * 16) * 2);\
        _Pragma("unroll") for (int nj = 0; nj < 2; nj++)                       \
            ldsm4t(bf[nj*2][0], bf[nj*2][1], bf[nj*2+1][0], bf[nj*2+1][1],     \
                   b_addr0 + (st) * BSZ * 2 + (ks16 * 16 * BSTR + nj * 16) * 2);\
        _Pragma("unroll") for (int mi = 0; mi < 4; mi++)                       \
        _Pragma("unroll") for (int ni = 0; ni < 4; ni++)                       \
            mma_bf16(acc[mi][ni], af[mi], bf[ni]);                             \
    }

// 3-stage, one barrier per iteration: buffer (it+2)%3 refilled after the
// barrier at iter it was last read at iter it-1 (before this barrier).
#define GEMM_MAINLOOP(Wb, ldk, KK, Xb)                                         \
    {                                                                          \
        const int nit = (KK) / 64;                                             \
        GEMM_CP(Wb, ldk, Xb, 0, 0);  CP_COMMIT();                              \
        GEMM_CP(Wb, ldk, Xb, 64, 1); CP_COMMIT();                              \
        int stg = 0;                                                           \
        for (int it = 0; it < nit; it++) {                                     \
            CP_WAIT1();                                                        \
            __syncthreads();                                                   \
            if (it + 2 < nit) {                                                \
                int st2 = stg + 2; if (st2 >= GST) st2 -= GST;                 \
                GEMM_CP(Wb, ldk, Xb, (it + 2) * 64, st2);                      \
            }                                                                  \
            CP_COMMIT();                                                       \
            GEMM_COMPUTE(stg);                                                 \
            if (++stg >= GST) stg -= GST;                                      \
        }                                                                      \
    }

// =============================================================================
// Merged GEMM1+GEMM2: grid.y 0..15 -> u/v (W_in, silu); 16..19 -> q/k (W_attn)
// =============================================================================
__global__ __launch_bounds__(256, 2) void gemm_uvqk_bf16(
    const float* __restrict__ b_in,
    const float* __restrict__ b_attn,
    const float* __restrict__ wq, const float* __restrict__ bq,
    const float* __restrict__ wk, const float* __restrict__ bk)
{
    GEMM_DECL();
    const __nv_bfloat16* xb = g_xb + (size_t)b * C_ * T_;
    const __nv_bfloat16* Ap = (m0 < 2 * E_)
        ? g_wi
        : g_wa - (size_t)(2 * E_) * C_;
    GEMM_MAINLOOP(Ap, C_, C_, xb);

    if (m0 < 2 * E_) {
        __nv_bfloat16* outp = (m0 < E_)
            ? g_u + (size_t)b * E_ * T_
            : g_v + (size_t)b * E_ * T_ - (size_t)E_ * T_;
#pragma unroll
        for (int mi = 0; mi < 4; mi++) {
            int m = m0 + wm + mi * 16 + g;
            float b0 = b_in[m], b1 = b_in[m + 8];
#pragma unroll
            for (int ni = 0; ni < 4; ni++) {
                int n = n0 + wn + ni * 8 + 2 * th4;
                float t0 = acc[mi][ni][0] + b0, t1 = acc[mi][ni][1] + b0;
                float t2 = acc[mi][ni][2] + b1, t3 = acc[mi][ni][3] + b1;
                unsigned w0 = packbf(t0 / (1.f + __expf(-t0)), t1 / (1.f + __expf(-t1)));
                unsigned w1 = packbf(t2 / (1.f + __expf(-t2)), t3 / (1.f + __expf(-t3)));
                *(unsigned*)(outp + (size_t)m * T_ + n)       = w0;
                *(unsigned*)(outp + (size_t)(m + 8) * T_ + n) = w1;
            }
        }
    } else {
        const int mq0 = m0 - 2 * E_;
        __nv_bfloat16* qp = g_q + (size_t)b * QK_ * T_;
        __nv_bfloat16* kp = g_k + (size_t)b * QK_ * T_;
#pragma unroll
        for (int mi = 0; mi < 4; mi++) {
            int m = mq0 + wm + mi * 16 + g;
            float bi0 = b_attn[m], bi1 = b_attn[m + 8];
            float wq0 = wq[m] * QSCALE_, bq0 = bq[m] * QSCALE_;
            float wk0 = wk[m], bk0 = bk[m];
            float wq1 = wq[m + 8] * QSCALE_, bq1 = bq[m + 8] * QSCALE_;
            float wk1 = wk[m + 8], bk1 = bk[m + 8];
#pragma unroll
            for (int ni = 0; ni < 4; ni++) {
                int n = n0 + wn + ni * 8 + 2 * th4;
                float z0 = acc[mi][ni][0] + bi0, z1 = acc[mi][ni][1] + bi0;
                float z2 = acc[mi][ni][2] + bi1, z3 = acc[mi][ni][3] + bi1;
                *(unsigned*)(qp + (size_t)m * T_ + n)       = packbf(z0 * wq0 + bq0, z1 * wq0 + bq0);
                *(unsigned*)(qp + (size_t)(m + 8) * T_ + n) = packbf(z2 * wq1 + bq1, z3 * wq1 + bq1);
                *(unsigned*)(kp + (size_t)m * T_ + n)       = packbf(z0 * wk0 + bk0, z1 * wk0 + bk0);
                *(unsigned*)(kp + (size_t)(m + 8) * T_ + n) = packbf(z2 * wk1 + bk1, z3 * wk1 + bk1);
            }
        }
    }
}

// =============================================================================
// Flash attention bf16, BQ=128 (8 warps x 16 rows), BKV=64,
// 3-stage cp.async KV pipeline, ONE barrier per tile, no-max exp2 softmax,
// fused u-gating epilogue. launch_bounds(256,2): regs<=128, 2 CTAs/SM.
// smem/CTA = 17408 + 3*27648 = 100352 B; 2 CTAs = 200704 <= 228KB.
// =============================================================================
#define QS2 136
#define KS2 72
#define KVB (192 * KS2 * 2)
#define QS_BYTES (64 * QS2 * 2)
#define AST 3
#define ATTN_SMEM (QS_BYTES + AST * KVB)

__global__ __launch_bounds__(256, 2) void attn_bf16_kernel()
{
    extern __shared__ __align__(16) char dsm[];
    unsigned short* qs = (unsigned short*)dsm;
    unsigned short* ks = (unsigned short*)(dsm + QS_BYTES);
    unsigned short* vs = ks + 64 * KS2;
    float* os = (float*)(dsm + QS_BYTES);   // epilogue alias (34816 <= 3*KVB)

    const int b  = blockIdx.z;
    const int h  = blockIdx.y;
    const int qt = blockIdx.x;
    const int tid = threadIdx.x;
    const int lane = tid & 31, warp = tid >> 5;
    const int g = lane >> 2, th4 = lane & 3;
    const int wq = warp * 16;

    const __nv_bfloat16* qbase = g_q + (size_t)(b * QK_ + h * HD_) * T_;
    const __nv_bfloat16* kbase = g_k + (size_t)(b * QK_ + h * HD_) * T_;
    const __nv_bfloat16* vbase = g_v + (size_t)(b * E_ + h * EV_) * T_;

    const unsigned qs_b = (unsigned)__cvta_generic_to_shared(qs);
    const unsigned ks_b = (unsigned)__cvta_generic_to_shared(ks);
    const unsigned vs_b = (unsigned)__cvta_generic_to_shared(vs);

    const unsigned qa0 = qs_b + ((((lane >> 4) << 3) + (lane & 7)) * QS2 + wq + (lane & 8)) * 2;
    const unsigned ka0 = ks_b + (((lane & 7) + ((lane >> 3) & 1) * 8) * KS2 + ((lane >> 4) & 1) * 8) * 2;
    const unsigned va0 = vs_b + (((lane & 7) + ((lane >> 4) & 1) * 8) * KS2 + (lane & 8)) * 2;

#pragma unroll
    for (int p = 0; p < 4; p++) {
        int idx = tid + 256 * p;
        int d  = idx >> 4;
        int q8 = (idx & 15) << 3;
        *(uint4*)&qs[d * QS2 + q8] =
            *(const uint4*)(qbase + (size_t)d * T_ + qt * 128 + q8);
    }

#define ATTN_CP_KV(kt0, st)                                                    \
    _Pragma("unroll") for (int p = 0; p < 2; p++) {                            \
        int idx = tid + 256 * p;                                               \
        int d  = idx >> 3;                                                     \
        int c8 = (idx & 7) << 3;                                               \
        cp16(ks_b + (st) * KVB + (d * KS2 + c8) * 2,                           \
             kbase + (size_t)d * T_ + (kt0) + c8);                             \
    }                                                                          \
    _Pragma("unroll") for (int p = 0; p < 4; p++) {                            \
        int idx = tid + 256 * p;                                               \
        int e  = idx >> 3;                                                     \
        int c8 = (idx & 7) << 3;                                               \
        cp16(vs_b + (st) * KVB + (e * KS2 + c8) * 2,                           \
             vbase + (size_t)e * T_ + (kt0) + c8);                             \
    }

    float o[16][4];
#pragma unroll
    for (int e = 0; e < 16; e++)
#pragma unroll
        for (int r = 0; r < 4; r++) o[e][r] = 0.f;
    float l_0 = 0.f, l_1 = 0.f;

    ATTN_CP_KV(0, 0);   CP_COMMIT();
    ATTN_CP_KV(64, 1);  CP_COMMIT();

    int stage = 0;
    for (int kt = 0; kt < 16; kt++) {
        CP_WAIT1();
        __syncthreads();
        if (kt + 2 < 16) {
            int st2 = stage + 2; if (st2 >= AST) st2 -= AST;
            ATTN_CP_KV((kt + 2) * 64, st2);
        }
        CP_COMMIT();
        const unsigned stoff = (unsigned)stage * KVB;

        float s[8][4];
#pragma unroll
        for (int ni = 0; ni < 8; ni++)
#pragma unroll
            for (int r = 0; r < 4; r++) s[ni][r] = 0.f;
#pragma unroll
        for (int kd = 0; kd < 4; kd++) {
            unsigned a[4];
            ldsm4t(a[0], a[1], a[2], a[3], qa0 + kd * 16 * QS2 * 2);
#pragma unroll
            for (int kvj = 0; kvj < 4; kvj++) {
                unsigned r0, r1, r2, r3;
                ldsm4t(r0, r1, r2, r3, ka0 + stoff + (kd * 16 * KS2 + kvj * 16) * 2);
                unsigned b0[2] = {r0, r1}, b1[2] = {r2, r3};
                mma_bf16(s[2 * kvj],     a, b0);
                mma_bf16(s[2 * kvj + 1], a, b1);
            }
        }

        unsigned pf[4][4];
#pragma unroll
        for (int j = 0; j < 4; j++) {
            float p00 = exp2f(s[2 * j][0]),     p01 = exp2f(s[2 * j][1]);
            float p02 = exp2f(s[2 * j][2]),     p03 = exp2f(s[2 * j][3]);
            float p10 = exp2f(s[2 * j + 1][0]), p11 = exp2f(s[2 * j + 1][1]);
            float p12 = exp2f(s[2 * j + 1][2]), p13 = exp2f(s[2 * j + 1][3]);
            l_0 += p00 + p01 + p10 + p11;
            l_1 += p02 + p03 + p12 + p13;
            pf[j][0] = packbf(p00, p01);
            pf[j][1] = packbf(p02, p03);
            pf[j][2] = packbf(p10, p11);
            pf[j][3] = packbf(p12, p13);
        }

#pragma unroll
        for (int j = 0; j < 4; j++) {
#pragma unroll
            for (int ej = 0; ej < 8; ej++) {
                unsigned r0, r1, r2, r3;
                ldsm4(r0, r1, r2, r3, va0 + stoff + (ej * 16 * KS2 + j * 16) * 2);
                unsigned b0[2] = {r0, r1}, b1[2] = {r2, r3};
                mma_bf16(o[2 * ej],     pf[j], b0);
                mma_bf16(o[2 * ej + 1], pf[j], b1);
            }
        }
        if (++stage >= AST) stage -= AST;
    }

    l_0 += __shfl_xor_sync(0xffffffffu, l_0, 1);
    l_0 += __shfl_xor_sync(0xffffffffu, l_0, 2);
    l_1 += __shfl_xor_sync(0xffffffffu, l_1, 1);
    l_1 += __shfl_xor_sync(0xffffffffu, l_1, 2);
    float inv0 = 1.f / l_0, inv1 = 1.f / l_1;
#pragma unroll
    for (int e = 0; e < 16; e++) {
        o[e][0] *= inv0; o[e][1] *= inv0;
        o[e][2] *= inv1; o[e][3] *= inv1;
    }

    // epilogue: two e-halves, transpose -> smem [e][t], fuse u-gating
    const __nv_bfloat16* ubase = g_u + (size_t)(b * E_ + h * EV_) * T_ + qt * 128;
    __nv_bfloat16* wbase = g_w + (size_t)(b * E_ + h * EV_) * T_ + qt * 128;
#pragma unroll
    for (int eh = 0; eh < 2; eh++) {
        __syncthreads();
#pragma unroll
        for (int et = eh * 8; et < eh * 8 + 8; et++) {
            int ec = et * 8 + 2 * th4 - eh * 64;
            os[ec * QS2 + wq + g]           = o[et][0];
            os[(ec + 1) * QS2 + wq + g]     = o[et][1];
            os[ec * QS2 + wq + g + 8]       = o[et][2];
            os[(ec + 1) * QS2 + wq + g + 8] = o[et][3];
        }
        __syncthreads();
#pragma unroll
        for (int p = 0; p < 4; p++) {
            int idx = tid + 256 * p;
            int e  = idx >> 4;
            int t8 = (idx & 15) << 3;
            int eg = eh * 64 + e;
            uint4 uv = *(const uint4*)(ubase + (size_t)eg * T_ + t8);
            const __nv_bfloat162* up = (const __nv_bfloat162*)&uv;
            const float* orow = os + e * QS2 + t8;
            float2 u0 = __bfloat1622float2(up[0]);
            float2 u1 = __bfloat1622float2(up[1]);
            float2 u2 = __bfloat1622float2(up[2]);
            float2 u3 = __bfloat1622float2(up[3]);
            uint4 wv = {
                packbf(u0.x * orow[0], u0.y * orow[1]),
                packbf(u1.x * orow[2], u1.y * orow[3]),
                packbf(u2.x * orow[4], u2.y * orow[5]),
                packbf(u3.x * orow[6], u3.y * orow[7])};
            *(uint4*)(wbase + (size_t)eg * T_ + t8) = wv;
        }
    }
}

// =============================================================================
// GEMM3: y = x + b_out + W_out @ w   M=512 K=1024 N=1024
// =============================================================================
__global__ __launch_bounds__(256, 2) void gemm_out_bf16(
    const float* __restrict__ x, const float* __restrict__ bias)
{
    GEMM_DECL();
    const __nv_bfloat16* wb = g_w + (size_t)b * E_ * T_;
    GEMM_MAINLOOP(g_wo, E_, E_, wb);
    const float* xb = x + (size_t)b * C_ * T_;
    float* yp = g_y + (size_t)b * C_ * T_;
#pragma unroll
    for (int mi = 0; mi < 4; mi++) {
        int m = m0 + wm + mi * 16 + g;
        float bo0 = bias[m], bo1 = bias[m + 8];
#pragma unroll
        for (int ni = 0; ni < 4; ni++) {
            int n = n0 + wn + ni * 8 + 2 * th4;
            float2 x0 = *(const float2*)(xb + (size_t)m * T_ + n);
            float2 x1 = *(const float2*)(xb + (size_t)(m + 8) * T_ + n);
            float2 y0 = {acc[mi][ni][0] + bo0 + x0.x, acc[mi][ni][1] + bo0 + x0.y};
            float2 y1 = {acc[mi][ni][2] + bo1 + x1.x, acc[mi][ni][3] + bo1 + x1.y};
            *(float2*)(yp + (size_t)m * T_ + n)       = y0;
            *(float2*)(yp + (size_t)(m + 8) * T_ + n) = y1;
        }
    }
}

// =============================================================================
// RMSNorm over C
// =============================================================================
__global__ __launch_bounds__(256) void rms2_kernel(
    const float* __restrict__ gamma, float* __restrict__ out)
{
    __shared__ float red[8][32];
    __shared__ float rbuf[32];
    const int b = blockIdx.y;
    const int tseg = threadIdx.x & 31, cseg = threadIdx.x >> 5;
    const int t = blockIdx.x * 32 + tseg;
    const float* yb = g_y + (size_t)b * C_ * T_ + t;
    float ss = 0.f;
#pragma unroll 8
    for (int c = cseg * 64; c < cseg * 64 + 64; c++) {
        float v = yb[(size_t)c * T_];
        ss += v * v;
    }
    red[cseg][tseg] = ss;
    __syncthreads();
    if (cseg == 0) {
        float tot = 0.f;
#pragma unroll
        for (int i = 0; i < 8; i++) tot += red[i][tseg];
        rbuf[tseg] = rsqrtf(tot * (1.f / C_) + 1e-5f);
    }
    __syncthreads();
    float r = rbuf[tseg];
    float* op = out + (size_t)b * C_ * T_ + t;
#pragma unroll 8
    for (int c = cseg * 64; c < cseg * 64 + 64; c++) {
        op[(size_t)c * T_] = yb[(size_t)c * T_] * r * gamma[c];
    }
}

// =============================================================================
// launch
// =============================================================================
extern "C" void kernel_launch(void* const* d_in, const int* in_sizes, int n_in,
                              void* d_out, int out_size)
{
    const float* x      = (const float*)d_in[0];
    const float* W_in   = (const float*)d_in[1];
    const float* b_in   = (const float*)d_in[2];
    const float* W_attn = (const float*)d_in[3];
    const float* b_attn = (const float*)d_in[4];
    const float* w_q    = (const float*)d_in[5];
    const float* b_q    = (const float*)d_in[6];
    const float* w_k    = (const float*)d_in[7];
    const float* b_k    = (const float*)d_in[8];
    const float* W_out  = (const float*)d_in[9];
    const float* b_out  = (const float*)d_in[10];
    const float* gamma  = (const float*)d_in[11];
    float* out = (float*)d_out;

    cudaFuncSetAttribute(gemm_uvqk_bf16,
                         cudaFuncAttributeMaxDynamicSharedMemorySize, GEMM_SMEM);
    cudaFuncSetAttribute(gemm_out_bf16,
                         cudaFuncAttributeMaxDynamicSharedMemorySize, GEMM_SMEM);
    cudaFuncSetAttribute(attn_bf16_kernel,
                         cudaFuncAttributeMaxDynamicSharedMemorySize, ATTN_SMEM);

    conv_all<<<CV3, 256>>>(W_in, W_attn, W_out, x);

    gemm_uvqk_bf16<<<dim3(T_ / 128, 20, B_), 256, GEMM_SMEM>>>(
        b_in, b_attn, w_q, b_q, w_k, b_k);
    attn_bf16_kernel<<<dim3(T_ / 128, H_, B_), 256, ATTN_SMEM>>>();
    gemm_out_bf16<<<dim3(T_ / 128, C_ / 128, B_), 256, GEMM_SMEM>>>(x, b_out);
    rms2_kernel<<<dim3(T_ / 32, B_), 256>>>(gamma, out);
}

// round 15
// speedup vs baseline: 1.2391x; 1.0268x over previous
#include <cuda_runtime.h>
#include <cuda_bf16.h>
#include <math.h>

#define B_  8
#define C_  512
#define T_  1024
#define E_  1024
#define H_  8
#define HD_ 64
#define QK_ 512
#define EV_ 128

// log(1024)/log(512)/sqrt(64) * log2(e)  (exp2-based softmax)
#define QSCALE_ 0.20037157933881626f

// ---------------- scratch (bf16 intermediates) ----------------
static __device__ __nv_bfloat16 g_u[(size_t)B_ * E_ * T_];
static __device__ __nv_bfloat16 g_v[(size_t)B_ * E_ * T_];
static __device__ __nv_bfloat16 g_q[(size_t)B_ * QK_ * T_];   // pre-scaled
static __device__ __nv_bfloat16 g_k[(size_t)B_ * QK_ * T_];
static __device__ __nv_bfloat16 g_w[(size_t)B_ * E_ * T_];
static __device__ float g_y[(size_t)B_ * C_ * T_];
static __device__ float g_ss[(size_t)B_ * T_];                // sum of y^2 over c
static __device__ __nv_bfloat16 g_wi[(size_t)2 * E_ * C_];
static __device__ __nv_bfloat16 g_wa[(size_t)QK_ * C_];
static __device__ __nv_bfloat16 g_wo[(size_t)C_ * E_];
static __device__ __nv_bfloat16 g_xb[(size_t)B_ * C_ * T_];

// ---------------- helpers ----------------
__device__ __forceinline__ unsigned packbf(float lo, float hi) {
    unsigned r;
    asm("cvt.rn.bf16x2.f32 %0, %1, %2;" : "=r"(r) : "f"(hi), "f"(lo));
    return r;
}
__device__ __forceinline__ void mma_bf16(float* d, const unsigned* a, const unsigned* b) {
    asm volatile(
        "mma.sync.aligned.m16n8k16.row.col.f32.bf16.bf16.f32 "
        "{%0,%1,%2,%3}, {%4,%5,%6,%7}, {%8,%9}, {%0,%1,%2,%3};"
        : "+f"(d[0]), "+f"(d[1]), "+f"(d[2]), "+f"(d[3])
        : "r"(a[0]), "r"(a[1]), "r"(a[2]), "r"(a[3]), "r"(b[0]), "r"(b[1]));
}
__device__ __forceinline__ void ldsm4(unsigned& r0, unsigned& r1, unsigned& r2, unsigned& r3,
                                      unsigned addr) {
    asm volatile("ldmatrix.sync.aligned.m8n8.x4.shared.b16 {%0,%1,%2,%3}, [%4];"
                 : "=r"(r0), "=r"(r1), "=r"(r2), "=r"(r3) : "r"(addr));
}
__device__ __forceinline__ void ldsm4t(unsigned& r0, unsigned& r1, unsigned& r2, unsigned& r3,
                                       unsigned addr) {
    asm volatile("ldmatrix.sync.aligned.m8n8.x4.trans.shared.b16 {%0,%1,%2,%3}, [%4];"
                 : "=r"(r0), "=r"(r1), "=r"(r2), "=r"(r3) : "r"(addr));
}
__device__ __forceinline__ void cp16(unsigned saddr, const void* gptr) {
    asm volatile("cp.async.cg.shared.global [%0], [%1], 16;"
                 :: "r"(saddr), "l"(gptr));
}
#define CP_COMMIT() asm volatile("cp.async.commit_group;" ::: "memory")
#define CP_WAIT1()  asm volatile("cp.async.wait_group 1;" ::: "memory")

// ---------------- fused fp32 -> bf16 conversion (all 4 tensors, 1 launch) ----
#define CV0 512
#define CV1 (CV0 + 128)
#define CV2 (CV1 + 256)
#define CV3 (CV2 + 2048)
__global__ __launch_bounds__(256) void conv_all(
    const float* __restrict__ s0, const float* __restrict__ s1,
    const float* __restrict__ s2, const float* __restrict__ s3)
{
    int blk = blockIdx.x;
    const float* src;
    __nv_bfloat16* dst;
    int rel;
    if      (blk < CV0) { src = s0; dst = g_wi; rel = blk; }
    else if (blk < CV1) { src = s1; dst = g_wa; rel = blk - CV0; }
    else if (blk < CV2) { src = s2; dst = g_wo; rel = blk - CV1; }
    else                { src = s3; dst = g_xb; rel = blk - CV2; }
    size_t i = ((size_t)rel * 256 + threadIdx.x) * 8;
    float4 a = *(const float4*)(src + i);
    float4 b = *(const float4*)(src + i + 4);
    uint4 w = {packbf(a.x, a.y), packbf(a.z, a.w), packbf(b.x, b.y), packbf(b.z, b.w)};
    *(uint4*)(dst + i) = w;
}

// ------- GEMM: 128x128 CTA, BK=64, 3-stage cp.async, ONE barrier per iter ----
#define ASTR 72
#define BSTR 136
#define ASZ (128 * ASTR)
#define BSZ (64 * BSTR)
#define GST 3
#define GEMM_SMEM ((GST * (ASZ + BSZ)) * 2)

#define GEMM_DECL()                                                            \
    extern __shared__ __align__(16) unsigned short gsm[];                      \
    unsigned short* As = gsm;                                                  \
    unsigned short* Bs = gsm + GST * ASZ;                                      \
    const int b   = blockIdx.z;                                                \
    const int m0  = blockIdx.y * 128;                                          \
    const int n0  = blockIdx.x * 128;                                          \
    const int tid = threadIdx.x;                                               \
    const int lane = tid & 31, warp = tid >> 5;                                \
    const int g = lane >> 2, th4 = lane & 3;                                   \
    const int wm = (warp & 1) * 64, wn = (warp >> 1) * 32;                     \
    const unsigned as_b = (unsigned)__cvta_generic_to_shared(As);              \
    const unsigned bs_b = (unsigned)__cvta_generic_to_shared(Bs);              \
    const unsigned a_addr0 = as_b + ((wm + (lane & 15)) * ASTR + (lane >> 4) * 8) * 2; \
    const unsigned b_addr0 = bs_b + ((lane & 15) * BSTR + wn + (lane >> 4) * 8) * 2;   \
    float acc[4][4][4];                                                        \
    _Pragma("unroll") for (int i = 0; i < 4; i++)                              \
    _Pragma("unroll") for (int j = 0; j < 4; j++)                              \
    _Pragma("unroll") for (int r = 0; r < 4; r++) acc[i][j][r] = 0.f;

#define GEMM_CP(Wb, ldk, Xb, k0, st)                                           \
    _Pragma("unroll") for (int p = 0; p < 4; p++) {                            \
        int idx = tid + 256 * p;                                               \
        cp16(as_b + (st) * ASZ * 2 + ((idx >> 3) * ASTR + (idx & 7) * 8) * 2,  \
             (Wb) + (size_t)(m0 + (idx >> 3)) * (ldk) + (k0) + (idx & 7) * 8); \
        cp16(bs_b + (st) * BSZ * 2 + ((idx >> 4) * BSTR + (idx & 15) * 8) * 2, \
             (Xb) + (size_t)((k0) + (idx >> 4)) * T_ + n0 + (idx & 15) * 8);   \
    }

#define GEMM_COMPUTE(st)                                                       \
    _Pragma("unroll") for (int ks16 = 0; ks16 < 4; ks16++) {                   \
        unsigned af[4][4], bf[4][2];                                           \
        _Pragma("unroll") for (int mi = 0; mi < 4; mi++)                       \
            ldsm4(af[mi][0], af[mi][1], af[mi][2], af[mi][3],                  \
                  a_addr0 + (st) * ASZ * 2 + (mi * 16 * ASTR + ks16 * 16) * 2);\
        _Pragma("unroll") for (int nj = 0; nj < 2; nj++)                       \
            ldsm4t(bf[nj*2][0], bf[nj*2][1], bf[nj*2+1][0], bf[nj*2+1][1],     \
                   b_addr0 + (st) * BSZ * 2 + (ks16 * 16 * BSTR + nj * 16) * 2);\
        _Pragma("unroll") for (int mi = 0; mi < 4; mi++)                       \
        _Pragma("unroll") for (int ni = 0; ni < 4; ni++)                       \
            mma_bf16(acc[mi][ni], af[mi], bf[ni]);                             \
    }

#define GEMM_MAINLOOP(Wb, ldk, KK, Xb)                                         \
    {                                                                          \
        const int nit = (KK) / 64;                                             \
        GEMM_CP(Wb, ldk, Xb, 0, 0);  CP_COMMIT();                              \
        GEMM_CP(Wb, ldk, Xb, 64, 1); CP_COMMIT();                              \
        int stg = 0;                                                           \
        for (int it = 0; it < nit; it++) {                                     \
            CP_WAIT1();                                                        \
            __syncthreads();                                                   \
            if (it + 2 < nit) {                                                \
                int st2 = stg + 2; if (st2 >= GST) st2 -= GST;                 \
                GEMM_CP(Wb, ldk, Xb, (it + 2) * 64, st2);                      \
            }                                                                  \
            CP_COMMIT();                                                       \
            GEMM_COMPUTE(stg);                                                 \
            if (++stg >= GST) stg -= GST;                                      \
        }                                                                      \
    }

// =============================================================================
// Merged GEMM1+GEMM2: grid.y 0..15 -> u/v (W_in, silu); 16..19 -> q/k (W_attn)
// =============================================================================
__global__ __launch_bounds__(256, 2) void gemm_uvqk_bf16(
    const float* __restrict__ b_in,
    const float* __restrict__ b_attn,
    const float* __restrict__ wq, const float* __restrict__ bq,
    const float* __restrict__ wk, const float* __restrict__ bk)
{
    GEMM_DECL();
    const __nv_bfloat16* xb = g_xb + (size_t)b * C_ * T_;
    const __nv_bfloat16* Ap = (m0 < 2 * E_)
        ? g_wi
        : g_wa - (size_t)(2 * E_) * C_;
    GEMM_MAINLOOP(Ap, C_, C_, xb);

    if (m0 < 2 * E_) {
        __nv_bfloat16* outp = (m0 < E_)
            ? g_u + (size_t)b * E_ * T_
            : g_v + (size_t)b * E_ * T_ - (size_t)E_ * T_;
#pragma unroll
        for (int mi = 0; mi < 4; mi++) {
            int m = m0 + wm + mi * 16 + g;
            float b0 = b_in[m], b1 = b_in[m + 8];
#pragma unroll
            for (int ni = 0; ni < 4; ni++) {
                int n = n0 + wn + ni * 8 + 2 * th4;
                float t0 = acc[mi][ni][0] + b0, t1 = acc[mi][ni][1] + b0;
                float t2 = acc[mi][ni][2] + b1, t3 = acc[mi][ni][3] + b1;
                unsigned w0 = packbf(t0 / (1.f + __expf(-t0)), t1 / (1.f + __expf(-t1)));
                unsigned w1 = packbf(t2 / (1.f + __expf(-t2)), t3 / (1.f + __expf(-t3)));
                *(unsigned*)(outp + (size_t)m * T_ + n)       = w0;
                *(unsigned*)(outp + (size_t)(m + 8) * T_ + n) = w1;
            }
        }
    } else {
        const int mq0 = m0 - 2 * E_;
        __nv_bfloat16* qp = g_q + (size_t)b * QK_ * T_;
        __nv_bfloat16* kp = g_k + (size_t)b * QK_ * T_;
#pragma unroll
        for (int mi = 0; mi < 4; mi++) {
            int m = mq0 + wm + mi * 16 + g;
            float bi0 = b_attn[m], bi1 = b_attn[m + 8];
            float wq0 = wq[m] * QSCALE_, bq0 = bq[m] * QSCALE_;
            float wk0 = wk[m], bk0 = bk[m];
            float wq1 = wq[m + 8] * QSCALE_, bq1 = bq[m + 8] * QSCALE_;
            float wk1 = wk[m + 8], bk1 = bk[m + 8];
#pragma unroll
            for (int ni = 0; ni < 4; ni++) {
                int n = n0 + wn + ni * 8 + 2 * th4;
                float z0 = acc[mi][ni][0] + bi0, z1 = acc[mi][ni][1] + bi0;
                float z2 = acc[mi][ni][2] + bi1, z3 = acc[mi][ni][3] + bi1;
                *(unsigned*)(qp + (size_t)m * T_ + n)       = packbf(z0 * wq0 + bq0, z1 * wq0 + bq0);
                *(unsigned*)(qp + (size_t)(m + 8) * T_ + n) = packbf(z2 * wq1 + bq1, z3 * wq1 + bq1);
                *(unsigned*)(kp + (size_t)m * T_ + n)       = packbf(z0 * wk0 + bk0, z1 * wk0 + bk0);
                *(unsigned*)(kp + (size_t)(m + 8) * T_ + n) = packbf(z2 * wk1 + bk1, z3 * wk1 + bk1);
            }
        }
    }
}

// =============================================================================
// Flash attention bf16, BQ=128 (8 warps x 16 rows), BKV=64,
// 3-stage cp.async KV pipeline, ONE barrier per tile, no-max exp2 softmax,
// Q FRAGMENTS HOISTED into registers (loop-invariant), fused u-gating epilogue.
// launch_bounds(256,2): 2 CTAs/SM.
// =============================================================================
#define QS2 136
#define KS2 72
#define KVB (192 * KS2 * 2)
#define QS_BYTES (64 * QS2 * 2)
#define AST 3
#define ATTN_SMEM (QS_BYTES + AST * KVB)

__global__ __launch_bounds__(256, 2) void attn_bf16_kernel()
{
    extern __shared__ __align__(16) char dsm[];
    unsigned short* qs = (unsigned short*)dsm;
    unsigned short* ks = (unsigned short*)(dsm + QS_BYTES);
    unsigned short* vs = ks + 64 * KS2;
    float* os = (float*)(dsm + QS_BYTES);   // epilogue alias

    const int b  = blockIdx.z;
    const int h  = blockIdx.y;
    const int qt = blockIdx.x;
    const int tid = threadIdx.x;
    const int lane = tid & 31, warp = tid >> 5;
    const int g = lane >> 2, th4 = lane & 3;
    const int wq = warp * 16;

    const __nv_bfloat16* qbase = g_q + (size_t)(b * QK_ + h * HD_) * T_;
    const __nv_bfloat16* kbase = g_k + (size_t)(b * QK_ + h * HD_) * T_;
    const __nv_bfloat16* vbase = g_v + (size_t)(b * E_ + h * EV_) * T_;

    const unsigned qs_b = (unsigned)__cvta_generic_to_shared(qs);
    const unsigned ks_b = (unsigned)__cvta_generic_to_shared(ks);
    const unsigned vs_b = (unsigned)__cvta_generic_to_shared(vs);

    const unsigned qa0 = qs_b + ((((lane >> 4) << 3) + (lane & 7)) * QS2 + wq + (lane & 8)) * 2;
    const unsigned ka0 = ks_b + (((lane & 7) + ((lane >> 3) & 1) * 8) * KS2 + ((lane >> 4) & 1) * 8) * 2;
    const unsigned va0 = vs_b + (((lane & 7) + ((lane >> 4) & 1) * 8) * KS2 + (lane & 8)) * 2;

#pragma unroll
    for (int p = 0; p < 4; p++) {
        int idx = tid + 256 * p;
        int d  = idx >> 4;
        int q8 = (idx & 15) << 3;
        *(uint4*)&qs[d * QS2 + q8] =
            *(const uint4*)(qbase + (size_t)d * T_ + qt * 128 + q8);
    }

#define ATTN_CP_KV(kt0, st)                                                    \
    _Pragma("unroll") for (int p = 0; p < 2; p++) {                            \
        int idx = tid + 256 * p;                                               \
        int d  = idx >> 3;                                                     \
        int c8 = (idx & 7) << 3;                                               \
        cp16(ks_b + (st) * KVB + (d * KS2 + c8) * 2,                           \
             kbase + (size_t)d * T_ + (kt0) + c8);                             \
    }                                                                          \
    _Pragma("unroll") for (int p = 0; p < 4; p++) {                            \
        int idx = tid + 256 * p;                                               \
        int e  = idx >> 3;                                                     \
        int c8 = (idx & 7) << 3;                                               \
        cp16(vs_b + (st) * KVB + (e * KS2 + c8) * 2,                           \
             vbase + (size_t)e * T_ + (kt0) + c8);                             \
    }

    float o[16][4];
#pragma unroll
    for (int e = 0; e < 16; e++)
#pragma unroll
        for (int r = 0; r < 4; r++) o[e][r] = 0.f;
    float l_0 = 0.f, l_1 = 0.f;

    ATTN_CP_KV(0, 0);   CP_COMMIT();
    ATTN_CP_KV(64, 1);  CP_COMMIT();
    __syncthreads();

    // hoist loop-invariant Q fragments (16 regs)
    unsigned aq[4][4];
#pragma unroll
    for (int kd = 0; kd < 4; kd++)
        ldsm4t(aq[kd][0], aq[kd][1], aq[kd][2], aq[kd][3], qa0 + kd * 16 * QS2 * 2);

    int stage = 0;
    for (int kt = 0; kt < 16; kt++) {
        CP_WAIT1();
        __syncthreads();
        if (kt + 2 < 16) {
            int st2 = stage + 2; if (st2 >= AST) st2 -= AST;
            ATTN_CP_KV((kt + 2) * 64, st2);
        }
        CP_COMMIT();
        const unsigned stoff = (unsigned)stage * KVB;

        float s[8][4];
#pragma unroll
        for (int ni = 0; ni < 8; ni++)
#pragma unroll
            for (int r = 0; r < 4; r++) s[ni][r] = 0.f;
#pragma unroll
        for (int kd = 0; kd < 4; kd++) {
#pragma unroll
            for (int kvj = 0; kvj < 4; kvj++) {
                unsigned r0, r1, r2, r3;
                ldsm4t(r0, r1, r2, r3, ka0 + stoff + (kd * 16 * KS2 + kvj * 16) * 2);
                unsigned b0[2] = {r0, r1}, b1[2] = {r2, r3};
                mma_bf16(s[2 * kvj],     aq[kd], b0);
                mma_bf16(s[2 * kvj + 1], aq[kd], b1);
            }
        }

        unsigned pf[4][4];
#pragma unroll
        for (int j = 0; j < 4; j++) {
            float p00 = exp2f(s[2 * j][0]),     p01 = exp2f(s[2 * j][1]);
            float p02 = exp2f(s[2 * j][2]),     p03 = exp2f(s[2 * j][3]);
            float p10 = exp2f(s[2 * j + 1][0]), p11 = exp2f(s[2 * j + 1][1]);
            float p12 = exp2f(s[2 * j + 1][2]), p13 = exp2f(s[2 * j + 1][3]);
            l_0 += p00 + p01 + p10 + p11;
            l_1 += p02 + p03 + p12 + p13;
            pf[j][0] = packbf(p00, p01);
            pf[j][1] = packbf(p02, p03);
            pf[j][2] = packbf(p10, p11);
            pf[j][3] = packbf(p12, p13);
        }

#pragma unroll
        for (int j = 0; j < 4; j++) {
#pragma unroll
            for (int ej = 0; ej < 8; ej++) {
                unsigned r0, r1, r2, r3;
                ldsm4(r0, r1, r2, r3, va0 + stoff + (ej * 16 * KS2 + j * 16) * 2);
                unsigned b0[2] = {r0, r1}, b1[2] = {r2, r3};
                mma_bf16(o[2 * ej],     pf[j], b0);
                mma_bf16(o[2 * ej + 1], pf[j], b1);
            }
        }
        if (++stage >= AST) stage -= AST;
    }

    l_0 += __shfl_xor_sync(0xffffffffu, l_0, 1);
    l_0 += __shfl_xor_sync(0xffffffffu, l_0, 2);
    l_1 += __shfl_xor_sync(0xffffffffu, l_1, 1);
    l_1 += __shfl_xor_sync(0xffffffffu, l_1, 2);
    float inv0 = 1.f / l_0, inv1 = 1.f / l_1;
#pragma unroll
    for (int e = 0; e < 16; e++) {
        o[e][0] *= inv0; o[e][1] *= inv0;
        o[e][2] *= inv1; o[e][3] *= inv1;
    }

    const __nv_bfloat16* ubase = g_u + (size_t)(b * E_ + h * EV_) * T_ + qt * 128;
    __nv_bfloat16* wbase = g_w + (size_t)(b * E_ + h * EV_) * T_ + qt * 128;
#pragma unroll
    for (int eh = 0; eh < 2; eh++) {
        __syncthreads();
#pragma unroll
        for (int et = eh * 8; et < eh * 8 + 8; et++) {
            int ec = et * 8 + 2 * th4 - eh * 64;
            os[ec * QS2 + wq + g]           = o[et][0];
            os[(ec + 1) * QS2 + wq + g]     = o[et][1];
            os[ec * QS2 + wq + g + 8]       = o[et][2];
            os[(ec + 1) * QS2 + wq + g + 8] = o[et][3];
        }
        __syncthreads();
#pragma unroll
        for (int p = 0; p < 4; p++) {
            int idx = tid + 256 * p;
            int e  = idx >> 4;
            int t8 = (idx & 15) << 3;
            int eg = eh * 64 + e;
            uint4 uv = *(const uint4*)(ubase + (size_t)eg * T_ + t8);
            const __nv_bfloat162* up = (const __nv_bfloat162*)&uv;
            const float* orow = os + e * QS2 + t8;
            float2 u0 = __bfloat1622float2(up[0]);
            float2 u1 = __bfloat1622float2(up[1]);
            float2 u2 = __bfloat1622float2(up[2]);
            float2 u3 = __bfloat1622float2(up[3]);
            uint4 wv = {
                packbf(u0.x * orow[0], u0.y * orow[1]),
                packbf(u1.x * orow[2], u1.y * orow[3]),
                packbf(u2.x * orow[4], u2.y * orow[5]),
                packbf(u3.x * orow[6], u3.y * orow[7])};
            *(uint4*)(wbase + (size_t)eg * T_ + t8) = wv;
        }
    }
}

// =============================================================================
// GEMM3: y = x + b_out + W_out @ w ; also accumulates ss[b][t] += y^2 (atomics)
// =============================================================================
__global__ __launch_bounds__(256, 2) void gemm_out_bf16(
    const float* __restrict__ x, const float* __restrict__ bias)
{
    GEMM_DECL();
    const __nv_bfloat16* wb = g_w + (size_t)b * E_ * T_;
    GEMM_MAINLOOP(g_wo, E_, E_, wb);
    const float* xb = x + (size_t)b * C_ * T_;
    float* yp = g_y + (size_t)b * C_ * T_;
    float* ssp = g_ss + (size_t)b * T_;
    float ss0[4], ss1[4];
#pragma unroll
    for (int ni = 0; ni < 4; ni++) { ss0[ni] = 0.f; ss1[ni] = 0.f; }
#pragma unroll
    for (int mi = 0; mi < 4; mi++) {
        int m = m0 + wm + mi * 16 + g;
        float bo0 = bias[m], bo1 = bias[m + 8];
#pragma unroll
        for (int ni = 0; ni < 4; ni++) {
            int n = n0 + wn + ni * 8 + 2 * th4;
            float2 x0 = *(const float2*)(xb + (size_t)m * T_ + n);
            float2 x1 = *(const float2*)(xb + (size_t)(m + 8) * T_ + n);
            float2 y0 = {acc[mi][ni][0] + bo0 + x0.x, acc[mi][ni][1] + bo0 + x0.y};
            float2 y1 = {acc[mi][ni][2] + bo1 + x1.x, acc[mi][ni][3] + bo1 + x1.y};
            ss0[ni] += y0.x * y0.x + y1.x * y1.x;
            ss1[ni] += y0.y * y0.y + y1.y * y1.y;
            *(float2*)(yp + (size_t)m * T_ + n)       = y0;
            *(float2*)(yp + (size_t)(m + 8) * T_ + n) = y1;
        }
    }
#pragma unroll
    for (int ni = 0; ni < 4; ni++) {
        int n = n0 + wn + ni * 8 + 2 * th4;
        atomicAdd(ssp + n,     ss0[ni]);
        atomicAdd(ssp + n + 1, ss1[ni]);
    }
}

// =============================================================================
// RMSNorm over C: ss precomputed by gemm_out, single read+write pass
// =============================================================================
__global__ __launch_bounds__(256) void rms2_kernel(
    const float* __restrict__ gamma, float* __restrict__ out)
{
    const int b = blockIdx.y;
    const int tseg = threadIdx.x & 31, cseg = threadIdx.x >> 5;
    const int t = blockIdx.x * 32 + tseg;
    const float* yb = g_y + (size_t)b * C_ * T_ + t;
    float r = rsqrtf(g_ss[(size_t)b * T_ + t] * (1.f / C_) + 1e-5f);
    float* op = out + (size_t)b * C_ * T_ + t;
#pragma unroll 8
    for (int c = cseg * 64; c < cseg * 64 + 64; c++) {
        op[(size_t)c * T_] = yb[(size_t)c * T_] * r * gamma[c];
    }
}

// =============================================================================
// launch
// =============================================================================
extern "C" void kernel_launch(void* const* d_in, const int* in_sizes, int n_in,
                              void* d_out, int out_size)
{
    const float* x      = (const float*)d_in[0];
    const float* W_in   = (const float*)d_in[1];
    const float* b_in   = (const float*)d_in[2];
    const float* W_attn = (const float*)d_in[3];
    const float* b_attn = (const float*)d_in[4];
    const float* w_q    = (const float*)d_in[5];
    const float* b_q    = (const float*)d_in[6];
    const float* w_k    = (const float*)d_in[7];
    const float* b_k    = (const float*)d_in[8];
    const float* W_out  = (const float*)d_in[9];
    const float* b_out  = (const float*)d_in[10];
    const float* gamma  = (const float*)d_in[11];
    float* out = (float*)d_out;

    cudaFuncSetAttribute(gemm_uvqk_bf16,
                         cudaFuncAttributeMaxDynamicSharedMemorySize, GEMM_SMEM);
    cudaFuncSetAttribute(gemm_out_bf16,
                         cudaFuncAttributeMaxDynamicSharedMemorySize, GEMM_SMEM);
    cudaFuncSetAttribute(attn_bf16_kernel,
                         cudaFuncAttributeMaxDynamicSharedMemorySize, ATTN_SMEM);

    void* pss = nullptr;
    cudaGetSymbolAddress(&pss, g_ss);
    cudaMemsetAsync(pss, 0, (size_t)B_ * T_ * sizeof(float));

    conv_all<<<CV3, 256>>>(W_in, W_attn, W_out, x);

    gemm_uvqk_bf16<<<dim3(T_ / 128, 20, B_), 256, GEMM_SMEM>>>(
        b_in, b_attn, w_q, b_q, w_k, b_k);
    attn_bf16_kernel<<<dim3(T_ / 128, H_, B_), 256, ATTN_SMEM>>>();
    gemm_out_bf16<<<dim3(T_ / 128, C_ / 128, B_), 256, GEMM_SMEM>>>(x, b_out);
    rms2_kernel<<<dim3(T_ / 32, B_), 256>>>(gamma, out);
}

// round 16
// speedup vs baseline: 1.2613x; 1.0179x over previous
#include <cuda_runtime.h>
#include <cuda_bf16.h>
#include <math.h>

#define B_  8
#define C_  512
#define T_  1024
#define E_  1024
#define H_  8
#define HD_ 64
#define QK_ 512
#define EV_ 128

// log(1024)/log(512)/sqrt(64) * log2(e)  (exp2-based softmax)
#define QSCALE_ 0.20037157933881626f
#define LOG2E_  1.4426950408889634f

// ---------------- scratch (bf16 intermediates) ----------------
static __device__ __nv_bfloat16 g_u[(size_t)B_ * E_ * T_];
static __device__ __nv_bfloat16 g_v[(size_t)B_ * E_ * T_];
static __device__ __nv_bfloat16 g_q[(size_t)B_ * QK_ * T_];   // pre-scaled
static __device__ __nv_bfloat16 g_k[(size_t)B_ * QK_ * T_];
static __device__ __nv_bfloat16 g_w[(size_t)B_ * E_ * T_];
static __device__ float g_y[(size_t)B_ * C_ * T_];
static __device__ float g_ss[(size_t)B_ * T_];                // sum of y^2 over c
static __device__ __nv_bfloat16 g_wi[(size_t)2 * E_ * C_];
static __device__ __nv_bfloat16 g_wa[(size_t)QK_ * C_];
static __device__ __nv_bfloat16 g_wo[(size_t)C_ * E_];
static __device__ __nv_bfloat16 g_xb[(size_t)B_ * C_ * T_];

// ---------------- helpers ----------------
__device__ __forceinline__ unsigned packbf(float lo, float hi) {
    unsigned r;
    asm("cvt.rn.bf16x2.f32 %0, %1, %2;" : "=r"(r) : "f"(hi), "f"(lo));
    return r;
}
__device__ __forceinline__ float ex2a(float x) {
    float r;
    asm("ex2.approx.ftz.f32 %0, %1;" : "=f"(r) : "f"(x));
    return r;
}
__device__ __forceinline__ float rcpa(float x) {
    float r;
    asm("rcp.approx.ftz.f32 %0, %1;" : "=f"(r) : "f"(x));
    return r;
}
__device__ __forceinline__ float silua(float t) {
    return t * rcpa(1.f + ex2a(-t * LOG2E_));
}
__device__ __forceinline__ void mma_bf16(float* d, const unsigned* a, const unsigned* b) {
    asm volatile(
        "mma.sync.aligned.m16n8k16.row.col.f32.bf16.bf16.f32 "
        "{%0,%1,%2,%3}, {%4,%5,%6,%7}, {%8,%9}, {%0,%1,%2,%3};"
        : "+f"(d[0]), "+f"(d[1]), "+f"(d[2]), "+f"(d[3])
        : "r"(a[0]), "r"(a[1]), "r"(a[2]), "r"(a[3]), "r"(b[0]), "r"(b[1]));
}
__device__ __forceinline__ void ldsm4(unsigned& r0, unsigned& r1, unsigned& r2, unsigned& r3,
                                      unsigned addr) {
    asm volatile("ldmatrix.sync.aligned.m8n8.x4.shared.b16 {%0,%1,%2,%3}, [%4];"
                 : "=r"(r0), "=r"(r1), "=r"(r2), "=r"(r3) : "r"(addr));
}
__device__ __forceinline__ void ldsm4t(unsigned& r0, unsigned& r1, unsigned& r2, unsigned& r3,
                                       unsigned addr) {
    asm volatile("ldmatrix.sync.aligned.m8n8.x4.trans.shared.b16 {%0,%1,%2,%3}, [%4];"
                 : "=r"(r0), "=r"(r1), "=r"(r2), "=r"(r3) : "r"(addr));
}
__device__ __forceinline__ void cp16(unsigned saddr, const void* gptr) {
    asm volatile("cp.async.cg.shared.global [%0], [%1], 16;"
                 :: "r"(saddr), "l"(gptr));
}
#define CP_COMMIT() asm volatile("cp.async.commit_group;" ::: "memory")
#define CP_WAIT1()  asm volatile("cp.async.wait_group 1;" ::: "memory")

// ---------------- fused fp32 -> bf16 conversion (all 4 tensors, 1 launch) ----
#define CV0 512
#define CV1 (CV0 + 128)
#define CV2 (CV1 + 256)
#define CV3 (CV2 + 2048)
__global__ __launch_bounds__(256) void conv_all(
    const float* __restrict__ s0, const float* __restrict__ s1,
    const float* __restrict__ s2, const float* __restrict__ s3)
{
    int blk = blockIdx.x;
    const float* src;
    __nv_bfloat16* dst;
    int rel;
    if      (blk < CV0) { src = s0; dst = g_wi; rel = blk; }
    else if (blk < CV1) { src = s1; dst = g_wa; rel = blk - CV0; }
    else if (blk < CV2) { src = s2; dst = g_wo; rel = blk - CV1; }
    else                { src = s3; dst = g_xb; rel = blk - CV2; }
    size_t i = ((size_t)rel * 256 + threadIdx.x) * 8;
    float4 a = *(const float4*)(src + i);
    float4 b = *(const float4*)(src + i + 4);
    uint4 w = {packbf(a.x, a.y), packbf(a.z, a.w), packbf(b.x, b.y), packbf(b.z, b.w)};
    *(uint4*)(dst + i) = w;
}

// ------- GEMM: 128x128 CTA, BK=64, 3-stage cp.async, ONE barrier per iter ----
#define ASTR 72
#define BSTR 136
#define ASZ (128 * ASTR)
#define BSZ (64 * BSTR)
#define GST 3
#define GEMM_SMEM ((GST * (ASZ + BSZ)) * 2)

#define GEMM_DECL()                                                            \
    extern __shared__ __align__(16) unsigned short gsm[];                      \
    unsigned short* As = gsm;                                                  \
    unsigned short* Bs = gsm + GST * ASZ;                                      \
    const int b   = blockIdx.z;                                                \
    const int m0  = blockIdx.y * 128;                                          \
    const int n0  = blockIdx.x * 128;                                          \
    const int tid = threadIdx.x;                                               \
    const int lane = tid & 31, warp = tid >> 5;                                \
    const int g = lane >> 2, th4 = lane & 3;                                   \
    const int wm = (warp & 1) * 64, wn = (warp >> 1) * 32;                     \
    const unsigned as_b = (unsigned)__cvta_generic_to_shared(As);              \
    const unsigned bs_b = (unsigned)__cvta_generic_to_shared(Bs);              \
    const unsigned a_addr0 = as_b + ((wm + (lane & 15)) * ASTR + (lane >> 4) * 8) * 2; \
    const unsigned b_addr0 = bs_b + ((lane & 15) * BSTR + wn + (lane >> 4) * 8) * 2;   \
    float acc[4][4][4];                                                        \
    _Pragma("unroll") for (int i = 0; i < 4; i++)                              \
    _Pragma("unroll") for (int j = 0; j < 4; j++)                              \
    _Pragma("unroll") for (int r = 0; r < 4; r++) acc[i][j][r] = 0.f;

#define GEMM_CP(Wb, ldk, Xb, k0, st)                                           \
    _Pragma("unroll") for (int p = 0; p < 4; p++) {                            \
        int idx = tid + 256 * p;                                               \
        cp16(as_b + (st) * ASZ * 2 + ((idx >> 3) * ASTR + (idx & 7) * 8) * 2,  \
             (Wb) + (size_t)(m0 + (idx >> 3)) * (ldk) + (k0) + (idx & 7) * 8); \
        cp16(bs_b + (st) * BSZ * 2 + ((idx >> 4) * BSTR + (idx & 15) * 8) * 2, \
             (Xb) + (size_t)((k0) + (idx >> 4)) * T_ + n0 + (idx & 15) * 8);   \
    }

#define GEMM_COMPUTE(st)                                                       \
    _Pragma("unroll") for (int ks16 = 0; ks16 < 4; ks16++) {                   \
        unsigned af[4][4], bf[4][2];                                           \
        _Pragma("unroll") for (int mi = 0; mi < 4; mi++)                       \
            ldsm4(af[mi][0], af[mi][1], af[mi][2], af[mi][3],                  \
                  a_addr0 + (st) * ASZ * 2 + (mi * 16 * ASTR + ks16 * 16) * 2);\
        _Pragma("unroll") for (int nj = 0; nj < 2; nj++)                       \
            ldsm4t(bf[nj*2][0], bf[nj*2][1], bf[nj*2+1][0], bf[nj*2+1][1],     \
                   b_addr0 + (st) * BSZ * 2 + (ks16 * 16 * BSTR + nj * 16) * 2);\
        _Pragma("unroll") for (int mi = 0; mi < 4; mi++)                       \
        _Pragma("unroll") for (int ni = 0; ni < 4; ni++)                       \
            mma_bf16(acc[mi][ni], af[mi], bf[ni]);                             \
    }

#define GEMM_MAINLOOP(Wb, ldk, KK, Xb)                                         \
    {                                                                          \
        const int nit = (KK) / 64;                                             \
        GEMM_CP(Wb, ldk, Xb, 0, 0);  CP_COMMIT();                              \
        GEMM_CP(Wb, ldk, Xb, 64, 1); CP_COMMIT();                              \
        int stg = 0;                                                           \
        for (int it = 0; it < nit; it++) {                                     \
            CP_WAIT1();                                                        \
            __syncthreads();                                                   \
            if (it + 2 < nit) {                                                \
                int st2 = stg + 2; if (st2 >= GST) st2 -= GST;                 \
                GEMM_CP(Wb, ldk, Xb, (it + 2) * 64, st2);                      \
            }                                                                  \
            CP_COMMIT();                                                       \
            GEMM_COMPUTE(stg);                                                 \
            if (++stg >= GST) stg -= GST;                                      \
        }                                                                      \
    }

// =============================================================================
// Merged GEMM1+GEMM2: grid.y 0..15 -> u/v (W_in, silu); 16..19 -> q/k (W_attn)
// =============================================================================
__global__ __launch_bounds__(256, 2) void gemm_uvqk_bf16(
    const float* __restrict__ b_in,
    const float* __restrict__ b_attn,
    const float* __restrict__ wq, const float* __restrict__ bq,
    const float* __restrict__ wk, const float* __restrict__ bk)
{
    GEMM_DECL();
    const __nv_bfloat16* xb = g_xb + (size_t)b * C_ * T_;
    const __nv_bfloat16* Ap = (m0 < 2 * E_)
        ? g_wi
        : g_wa - (size_t)(2 * E_) * C_;
    GEMM_MAINLOOP(Ap, C_, C_, xb);

    if (m0 < 2 * E_) {
        __nv_bfloat16* outp = (m0 < E_)
            ? g_u + (size_t)b * E_ * T_
            : g_v + (size_t)b * E_ * T_ - (size_t)E_ * T_;
#pragma unroll
        for (int mi = 0; mi < 4; mi++) {
            int m = m0 + wm + mi * 16 + g;
            float b0 = b_in[m], b1 = b_in[m + 8];
#pragma unroll
            for (int ni = 0; ni < 4; ni++) {
                int n = n0 + wn + ni * 8 + 2 * th4;
                float t0 = acc[mi][ni][0] + b0, t1 = acc[mi][ni][1] + b0;
                float t2 = acc[mi][ni][2] + b1, t3 = acc[mi][ni][3] + b1;
                unsigned w0 = packbf(silua(t0), silua(t1));
                unsigned w1 = packbf(silua(t2), silua(t3));
                *(unsigned*)(outp + (size_t)m * T_ + n)       = w0;
                *(unsigned*)(outp + (size_t)(m + 8) * T_ + n) = w1;
            }
        }
    } else {
        const int mq0 = m0 - 2 * E_;
        __nv_bfloat16* qp = g_q + (size_t)b * QK_ * T_;
        __nv_bfloat16* kp = g_k + (size_t)b * QK_ * T_;
#pragma unroll
        for (int mi = 0; mi < 4; mi++) {
            int m = mq0 + wm + mi * 16 + g;
            float bi0 = b_attn[m], bi1 = b_attn[m + 8];
            float wq0 = wq[m] * QSCALE_, bq0 = bq[m] * QSCALE_;
            float wk0 = wk[m], bk0 = bk[m];
            float wq1 = wq[m + 8] * QSCALE_, bq1 = bq[m + 8] * QSCALE_;
            float wk1 = wk[m + 8], bk1 = bk[m + 8];
#pragma unroll
            for (int ni = 0; ni < 4; ni++) {
                int n = n0 + wn + ni * 8 + 2 * th4;
                float z0 = acc[mi][ni][0] + bi0, z1 = acc[mi][ni][1] + bi0;
                float z2 = acc[mi][ni][2] + bi1, z3 = acc[mi][ni][3] + bi1;
                *(unsigned*)(qp + (size_t)m * T_ + n)       = packbf(z0 * wq0 + bq0, z1 * wq0 + bq0);
                *(unsigned*)(qp + (size_t)(m + 8) * T_ + n) = packbf(z2 * wq1 + bq1, z3 * wq1 + bq1);
                *(unsigned*)(kp + (size_t)m * T_ + n)       = packbf(z0 * wk0 + bk0, z1 * wk0 + bk0);
                *(unsigned*)(kp + (size_t)(m + 8) * T_ + n) = packbf(z2 * wk1 + bk1, z3 * wk1 + bk1);
            }
        }
    }
}

// =============================================================================
// Flash attention bf16, BQ=128 (8 warps x 16 rows), BKV=64,
// 3-stage cp.async KV pipeline, ONE barrier per tile, no-max exp2 softmax
// (ex2.approx), Q fragments hoisted, fused u-gating epilogue. 2 CTAs/SM.
// =============================================================================
#define QS2 136
#define KS2 72
#define KVB (192 * KS2 * 2)
#define QS_BYTES (64 * QS2 * 2)
#define AST 3
#define ATTN_SMEM (QS_BYTES + AST * KVB)

__global__ __launch_bounds__(256, 2) void attn_bf16_kernel()
{
    extern __shared__ __align__(16) char dsm[];
    unsigned short* qs = (unsigned short*)dsm;
    unsigned short* ks = (unsigned short*)(dsm + QS_BYTES);
    unsigned short* vs = ks + 64 * KS2;
    float* os = (float*)(dsm + QS_BYTES);   // epilogue alias

    const int b  = blockIdx.z;
    const int h  = blockIdx.y;
    const int qt = blockIdx.x;
    const int tid = threadIdx.x;
    const int lane = tid & 31, warp = tid >> 5;
    const int g = lane >> 2, th4 = lane & 3;
    const int wq = warp * 16;

    const __nv_bfloat16* qbase = g_q + (size_t)(b * QK_ + h * HD_) * T_;
    const __nv_bfloat16* kbase = g_k + (size_t)(b * QK_ + h * HD_) * T_;
    const __nv_bfloat16* vbase = g_v + (size_t)(b * E_ + h * EV_) * T_;

    const unsigned qs_b = (unsigned)__cvta_generic_to_shared(qs);
    const unsigned ks_b = (unsigned)__cvta_generic_to_shared(ks);
    const unsigned vs_b = (unsigned)__cvta_generic_to_shared(vs);

    const unsigned qa0 = qs_b + ((((lane >> 4) << 3) + (lane & 7)) * QS2 + wq + (lane & 8)) * 2;
    const unsigned ka0 = ks_b + (((lane & 7) + ((lane >> 3) & 1) * 8) * KS2 + ((lane >> 4) & 1) * 8) * 2;
    const unsigned va0 = vs_b + (((lane & 7) + ((lane >> 4) & 1) * 8) * KS2 + (lane & 8)) * 2;

#pragma unroll
    for (int p = 0; p < 4; p++) {
        int idx = tid + 256 * p;
        int d  = idx >> 4;
        int q8 = (idx & 15) << 3;
        *(uint4*)&qs[d * QS2 + q8] =
            *(const uint4*)(qbase + (size_t)d * T_ + qt * 128 + q8);
    }

#define ATTN_CP_KV(kt0, st)                                                    \
    _Pragma("unroll") for (int p = 0; p < 2; p++) {                            \
        int idx = tid + 256 * p;                                               \
        int d  = idx >> 3;                                                     \
        int c8 = (idx & 7) << 3;                                               \
        cp16(ks_b + (st) * KVB + (d * KS2 + c8) * 2,                           \
             kbase + (size_t)d * T_ + (kt0) + c8);                             \
    }                                                                          \
    _Pragma("unroll") for (int p = 0; p < 4; p++) {                            \
        int idx = tid + 256 * p;                                               \
        int e  = idx >> 3;                                                     \
        int c8 = (idx & 7) << 3;                                               \
        cp16(vs_b + (st) * KVB + (e * KS2 + c8) * 2,                           \
             vbase + (size_t)e * T_ + (kt0) + c8);                             \
    }

    float o[16][4];
#pragma unroll
    for (int e = 0; e < 16; e++)
#pragma unroll
        for (int r = 0; r < 4; r++) o[e][r] = 0.f;
    float l_0 = 0.f, l_1 = 0.f;

    ATTN_CP_KV(0, 0);   CP_COMMIT();
    ATTN_CP_KV(64, 1);  CP_COMMIT();
    __syncthreads();

    unsigned aq[4][4];
#pragma unroll
    for (int kd = 0; kd < 4; kd++)
        ldsm4t(aq[kd][0], aq[kd][1], aq[kd][2], aq[kd][3], qa0 + kd * 16 * QS2 * 2);

    int stage = 0;
    for (int kt = 0; kt < 16; kt++) {
        CP_WAIT1();
        __syncthreads();
        if (kt + 2 < 16) {
            int st2 = stage + 2; if (st2 >= AST) st2 -= AST;
            ATTN_CP_KV((kt + 2) * 64, st2);
        }
        CP_COMMIT();
        const unsigned stoff = (unsigned)stage * KVB;

        float s[8][4];
#pragma unroll
        for (int ni = 0; ni < 8; ni++)
#pragma unroll
            for (int r = 0; r < 4; r++) s[ni][r] = 0.f;
#pragma unroll
        for (int kd = 0; kd < 4; kd++) {
#pragma unroll
            for (int kvj = 0; kvj < 4; kvj++) {
                unsigned r0, r1, r2, r3;
                ldsm4t(r0, r1, r2, r3, ka0 + stoff + (kd * 16 * KS2 + kvj * 16) * 2);
                unsigned b0[2] = {r0, r1}, b1[2] = {r2, r3};
                mma_bf16(s[2 * kvj],     aq[kd], b0);
                mma_bf16(s[2 * kvj + 1], aq[kd], b1);
            }
        }

        unsigned pf[4][4];
#pragma unroll
        for (int j = 0; j < 4; j++) {
            float p00 = ex2a(s[2 * j][0]),     p01 = ex2a(s[2 * j][1]);
            float p02 = ex2a(s[2 * j][2]),     p03 = ex2a(s[2 * j][3]);
            float p10 = ex2a(s[2 * j + 1][0]), p11 = ex2a(s[2 * j + 1][1]);
            float p12 = ex2a(s[2 * j + 1][2]), p13 = ex2a(s[2 * j + 1][3]);
            l_0 += p00 + p01 + p10 + p11;
            l_1 += p02 + p03 + p12 + p13;
            pf[j][0] = packbf(p00, p01);
            pf[j][1] = packbf(p02, p03);
            pf[j][2] = packbf(p10, p11);
            pf[j][3] = packbf(p12, p13);
        }

#pragma unroll
        for (int j = 0; j < 4; j++) {
#pragma unroll
            for (int ej = 0; ej < 8; ej++) {
                unsigned r0, r1, r2, r3;
                ldsm4(r0, r1, r2, r3, va0 + stoff + (ej * 16 * KS2 + j * 16) * 2);
                unsigned b0[2] = {r0, r1}, b1[2] = {r2, r3};
                mma_bf16(o[2 * ej],     pf[j], b0);
                mma_bf16(o[2 * ej + 1], pf[j], b1);
            }
        }
        if (++stage >= AST) stage -= AST;
    }

    l_0 += __shfl_xor_sync(0xffffffffu, l_0, 1);
    l_0 += __shfl_xor_sync(0xffffffffu, l_0, 2);
    l_1 += __shfl_xor_sync(0xffffffffu, l_1, 1);
    l_1 += __shfl_xor_sync(0xffffffffu, l_1, 2);
    float inv0 = rcpa(l_0), inv1 = rcpa(l_1);
#pragma unroll
    for (int e = 0; e < 16; e++) {
        o[e][0] *= inv0; o[e][1] *= inv0;
        o[e][2] *= inv1; o[e][3] *= inv1;
    }

    const __nv_bfloat16* ubase = g_u + (size_t)(b * E_ + h * EV_) * T_ + qt * 128;
    __nv_bfloat16* wbase = g_w + (size_t)(b * E_ + h * EV_) * T_ + qt * 128;
#pragma unroll
    for (int eh = 0; eh < 2; eh++) {
        __syncthreads();
#pragma unroll
        for (int et = eh * 8; et < eh * 8 + 8; et++) {
            int ec = et * 8 + 2 * th4 - eh * 64;
            os[ec * QS2 + wq + g]           = o[et][0];
            os[(ec + 1) * QS2 + wq + g]     = o[et][1];
            os[ec * QS2 + wq + g + 8]       = o[et][2];
            os[(ec + 1) * QS2 + wq + g + 8] = o[et][3];
        }
        __syncthreads();
#pragma unroll
        for (int p = 0; p < 4; p++) {
            int idx = tid + 256 * p;
            int e  = idx >> 4;
            int t8 = (idx & 15) << 3;
            int eg = eh * 64 + e;
            uint4 uv = *(const uint4*)(ubase + (size_t)eg * T_ + t8);
            const __nv_bfloat162* up = (const __nv_bfloat162*)&uv;
            const float* orow = os + e * QS2 + t8;
            float2 u0 = __bfloat1622float2(up[0]);
            float2 u1 = __bfloat1622float2(up[1]);
            float2 u2 = __bfloat1622float2(up[2]);
            float2 u3 = __bfloat1622float2(up[3]);
            uint4 wv = {
                packbf(u0.x * orow[0], u0.y * orow[1]),
                packbf(u1.x * orow[2], u1.y * orow[3]),
                packbf(u2.x * orow[4], u2.y * orow[5]),
                packbf(u3.x * orow[6], u3.y * orow[7])};
            *(uint4*)(wbase + (size_t)eg * T_ + t8) = wv;
        }
    }
}

// =============================================================================
// GEMM3: y = x + b_out + W_out @ w ; also accumulates ss[b][t] += y^2 (atomics)
// =============================================================================
__global__ __launch_bounds__(256, 2) void gemm_out_bf16(
    const float* __restrict__ x, const float* __restrict__ bias)
{
    GEMM_DECL();
    const __nv_bfloat16* wb = g_w + (size_t)b * E_ * T_;
    GEMM_MAINLOOP(g_wo, E_, E_, wb);
    const float* xb = x + (size_t)b * C_ * T_;
    float* yp = g_y + (size_t)b * C_ * T_;
    float* ssp = g_ss + (size_t)b * T_;
    float ss0[4], ss1[4];
#pragma unroll
    for (int ni = 0; ni < 4; ni++) { ss0[ni] = 0.f; ss1[ni] = 0.f; }
#pragma unroll
    for (int mi = 0; mi < 4; mi++) {
        int m = m0 + wm + mi * 16 + g;
        float bo0 = bias[m], bo1 = bias[m + 8];
#pragma unroll
        for (int ni = 0; ni < 4; ni++) {
            int n = n0 + wn + ni * 8 + 2 * th4;
            float2 x0 = *(const float2*)(xb + (size_t)m * T_ + n);
            float2 x1 = *(const float2*)(xb + (size_t)(m + 8) * T_ + n);
            float2 y0 = {acc[mi][ni][0] + bo0 + x0.x, acc[mi][ni][1] + bo0 + x0.y};
            float2 y1 = {acc[mi][ni][2] + bo1 + x1.x, acc[mi][ni][3] + bo1 + x1.y};
            ss0[ni] += y0.x * y0.x + y1.x * y1.x;
            ss1[ni] += y0.y * y0.y + y1.y * y1.y;
            *(float2*)(yp + (size_t)m * T_ + n)       = y0;
            *(float2*)(yp + (size_t)(m + 8) * T_ + n) = y1;
        }
    }
#pragma unroll
    for (int ni = 0; ni < 4; ni++) {
        int n = n0 + wn + ni * 8 + 2 * th4;
        atomicAdd(ssp + n,     ss0[ni]);
        atomicAdd(ssp + n + 1, ss1[ni]);
    }
}

// =============================================================================
// RMSNorm over C: ss precomputed by gemm_out, single read+write pass
// =============================================================================
__global__ __launch_bounds__(256) void rms2_kernel(
    const float* __restrict__ gamma, float* __restrict__ out)
{
    const int b = blockIdx.y;
    const int tseg = threadIdx.x & 31, cseg = threadIdx.x >> 5;
    const int t = blockIdx.x * 32 + tseg;
    const float* yb = g_y + (size_t)b * C_ * T_ + t;
    float r = rsqrtf(g_ss[(size_t)b * T_ + t] * (1.f / C_) + 1e-5f);
    float* op = out + (size_t)b * C_ * T_ + t;
#pragma unroll 8
    for (int c = cseg * 64; c < cseg * 64 + 64; c++) {
        op[(size_t)c * T_] = yb[(size_t)c * T_] * r * gamma[c];
    }
}

// =============================================================================
// launch
// =============================================================================
extern "C" void kernel_launch(void* const* d_in, const int* in_sizes, int n_in,
                              void* d_out, int out_size)
{
    const float* x      = (const float*)d_in[0];
    const float* W_in   = (const float*)d_in[1];
    const float* b_in   = (const float*)d_in[2];
    const float* W_attn = (const float*)d_in[3];
    const float* b_attn = (const float*)d_in[4];
    const float* w_q    = (const float*)d_in[5];
    const float* b_q    = (const float*)d_in[6];
    const float* w_k    = (const float*)d_in[7];
    const float* b_k    = (const float*)d_in[8];
    const float* W_out  = (const float*)d_in[9];
    const float* b_out  = (const float*)d_in[10];
    const float* gamma  = (const float*)d_in[11];
    float* out = (float*)d_out;

    cudaFuncSetAttribute(gemm_uvqk_bf16,
                         cudaFuncAttributeMaxDynamicSharedMemorySize, GEMM_SMEM);
    cudaFuncSetAttribute(gemm_out_bf16,
                         cudaFuncAttributeMaxDynamicSharedMemorySize, GEMM_SMEM);
    cudaFuncSetAttribute(attn_bf16_kernel,
                         cudaFuncAttributeMaxDynamicSharedMemorySize, ATTN_SMEM);

    void* pss = nullptr;
    cudaGetSymbolAddress(&pss, g_ss);
    cudaMemsetAsync(pss, 0, (size_t)B_ * T_ * sizeof(float));

    conv_all<<<CV3, 256>>>(W_in, W_attn, W_out, x);

    gemm_uvqk_bf16<<<dim3(T_ / 128, 20, B_), 256, GEMM_SMEM>>>(
        b_in, b_attn, w_q, b_q, w_k, b_k);
    attn_bf16_kernel<<<dim3(T_ / 128, H_, B_), 256, ATTN_SMEM>>>();
    gemm_out_bf16<<<dim3(T_ / 128, C_ / 128, B_), 256, GEMM_SMEM>>>(x, b_out);
    rms2_kernel<<<dim3(T_ / 32, B_), 256>>>(gamma, out);
}

// round 17
// speedup vs baseline: 1.2844x; 1.0183x over previous
#include <cuda_runtime.h>
#include <cuda_bf16.h>
#include <math.h>

#define B_  8
#define C_  512
#define T_  1024
#define E_  1024
#define H_  8
#define HD_ 64
#define QK_ 512
#define EV_ 128

// log(1024)/log(512)/sqrt(64) * log2(e)  (exp2-based softmax)
#define QSCALE_ 0.20037157933881626f
#define LOG2E_  1.4426950408889634f

// ---------------- scratch (bf16 intermediates) ----------------
static __device__ __nv_bfloat16 g_u[(size_t)B_ * E_ * T_];
static __device__ __nv_bfloat16 g_v[(size_t)B_ * E_ * T_];
static __device__ __nv_bfloat16 g_q[(size_t)B_ * QK_ * T_];   // pre-scaled
static __device__ __nv_bfloat16 g_k[(size_t)B_ * QK_ * T_];
static __device__ __nv_bfloat16 g_w[(size_t)B_ * E_ * T_];
static __device__ float g_y[(size_t)B_ * C_ * T_];
static __device__ float g_ss[(size_t)B_ * T_];                // sum of y^2 over c
static __device__ __nv_bfloat16 g_wi[(size_t)2 * E_ * C_];
static __device__ __nv_bfloat16 g_wa[(size_t)QK_ * C_];
static __device__ __nv_bfloat16 g_wo[(size_t)C_ * E_];
static __device__ __nv_bfloat16 g_xb[(size_t)B_ * C_ * T_];

// ---------------- helpers ----------------
__device__ __forceinline__ unsigned packbf(float lo, float hi) {
    unsigned r;
    asm("cvt.rn.bf16x2.f32 %0, %1, %2;" : "=r"(r) : "f"(hi), "f"(lo));
    return r;
}
__device__ __forceinline__ float ex2a(float x) {
    float r;
    asm("ex2.approx.ftz.f32 %0, %1;" : "=f"(r) : "f"(x));
    return r;
}
__device__ __forceinline__ float rcpa(float x) {
    float r;
    asm("rcp.approx.ftz.f32 %0, %1;" : "=f"(r) : "f"(x));
    return r;
}
__device__ __forceinline__ float silua(float t) {
    return t * rcpa(1.f + ex2a(-t * LOG2E_));
}
__device__ __forceinline__ void mma_bf16(float* d, const unsigned* a, const unsigned* b) {
    asm volatile(
        "mma.sync.aligned.m16n8k16.row.col.f32.bf16.bf16.f32 "
        "{%0,%1,%2,%3}, {%4,%5,%6,%7}, {%8,%9}, {%0,%1,%2,%3};"
        : "+f"(d[0]), "+f"(d[1]), "+f"(d[2]), "+f"(d[3])
        : "r"(a[0]), "r"(a[1]), "r"(a[2]), "r"(a[3]), "r"(b[0]), "r"(b[1]));
}
__device__ __forceinline__ void ldsm4(unsigned& r0, unsigned& r1, unsigned& r2, unsigned& r3,
                                      unsigned addr) {
    asm volatile("ldmatrix.sync.aligned.m8n8.x4.shared.b16 {%0,%1,%2,%3}, [%4];"
                 : "=r"(r0), "=r"(r1), "=r"(r2), "=r"(r3) : "r"(addr));
}
__device__ __forceinline__ void ldsm4t(unsigned& r0, unsigned& r1, unsigned& r2, unsigned& r3,
                                       unsigned addr) {
    asm volatile("ldmatrix.sync.aligned.m8n8.x4.trans.shared.b16 {%0,%1,%2,%3}, [%4];"
                 : "=r"(r0), "=r"(r1), "=r"(r2), "=r"(r3) : "r"(addr));
}
__device__ __forceinline__ void cp16(unsigned saddr, const void* gptr) {
    asm volatile("cp.async.cg.shared.global [%0], [%1], 16;"
                 :: "r"(saddr), "l"(gptr));
}
#define CP_COMMIT() asm volatile("cp.async.commit_group;" ::: "memory")
#define CP_WAIT1()  asm volatile("cp.async.wait_group 1;" ::: "memory")

// ---------------- fused fp32 -> bf16 conversion (all 4 tensors, 1 launch) ----
#define CV0 512
#define CV1 (CV0 + 128)
#define CV2 (CV1 + 256)
#define CV3 (CV2 + 2048)
__global__ __launch_bounds__(256) void conv_all(
    const float* __restrict__ s0, const float* __restrict__ s1,
    const float* __restrict__ s2, const float* __restrict__ s3)
{
    int blk = blockIdx.x;
    const float* src;
    __nv_bfloat16* dst;
    int rel;
    if      (blk < CV0) { src = s0; dst = g_wi; rel = blk; }
    else if (blk < CV1) { src = s1; dst = g_wa; rel = blk - CV0; }
    else if (blk < CV2) { src = s2; dst = g_wo; rel = blk - CV1; }
    else                { src = s3; dst = g_xb; rel = blk - CV2; }
    size_t i = ((size_t)rel * 256 + threadIdx.x) * 8;
    float4 a = *(const float4*)(src + i);
    float4 b = *(const float4*)(src + i + 4);
    uint4 w = {packbf(a.x, a.y), packbf(a.z, a.w), packbf(b.x, b.y), packbf(b.z, b.w)};
    *(uint4*)(dst + i) = w;
}

// ------- GEMM: 128x128 CTA, BK=64, 3-stage cp.async, ONE barrier per iter ----
#define ASTR 72
#define BSTR 136
#define ASZ (128 * ASTR)
#define BSZ (64 * BSTR)
#define GST 3
#define GEMM_SMEM ((GST * (ASZ + BSZ)) * 2)

#define GEMM_DECL()                                                            \
    extern __shared__ __align__(16) unsigned short gsm[];                      \
    unsigned short* As = gsm;                                                  \
    unsigned short* Bs = gsm + GST * ASZ;                                      \
    const int b   = blockIdx.z;                                                \
    const int m0  = blockIdx.y * 128;                                          \
    const int n0  = blockIdx.x * 128;                                          \
    const int tid = threadIdx.x;                                               \
    const int lane = tid & 31, warp = tid >> 5;                                \
    const int g = lane >> 2, th4 = lane & 3;                                   \
    const int wm = (warp & 1) * 64, wn = (warp >> 1) * 32;                     \
    const unsigned as_b = (unsigned)__cvta_generic_to_shared(As);              \
    const unsigned bs_b = (unsigned)__cvta_generic_to_shared(Bs);              \
    const unsigned a_addr0 = as_b + ((wm + (lane & 15)) * ASTR + (lane >> 4) * 8) * 2; \
    const unsigned b_addr0 = bs_b + ((lane & 15) * BSTR + wn + (lane >> 4) * 8) * 2;   \
    float acc[4][4][4];                                                        \
    _Pragma("unroll") for (int i = 0; i < 4; i++)                              \
    _Pragma("unroll") for (int j = 0; j < 4; j++)                              \
    _Pragma("unroll") for (int r = 0; r < 4; r++) acc[i][j][r] = 0.f;

#define GEMM_CP(Wb, ldk, Xb, k0, st)                                           \
    _Pragma("unroll") for (int p = 0; p < 4; p++) {                            \
        int idx = tid + 256 * p;                                               \
        cp16(as_b + (st) * ASZ * 2 + ((idx >> 3) * ASTR + (idx & 7) * 8) * 2,  \
             (Wb) + (size_t)(m0 + (idx >> 3)) * (ldk) + (k0) + (idx & 7) * 8); \
        cp16(bs_b + (st) * BSZ * 2 + ((idx >> 4) * BSTR + (idx & 15) * 8) * 2, \
             (Xb) + (size_t)((k0) + (idx >> 4)) * T_ + n0 + (idx & 15) * 8);   \
    }

#define GEMM_COMPUTE(st)                                                       \
    _Pragma("unroll") for (int ks16 = 0; ks16 < 4; ks16++) {                   \
        unsigned af[4][4], bf[4][2];                                           \
        _Pragma("unroll") for (int mi = 0; mi < 4; mi++)                       \
            ldsm4(af[mi][0], af[mi][1], af[mi][2], af[mi][3],                  \
                  a_addr0 + (st) * ASZ * 2 + (mi * 16 * ASTR + ks16 * 16) * 2);\
        _Pragma("unroll") for (int nj = 0; nj < 2; nj++)                       \
            ldsm4t(bf[nj*2][0], bf[nj*2][1], bf[nj*2+1][0], bf[nj*2+1][1],     \
                   b_addr0 + (st) * BSZ * 2 + (ks16 * 16 * BSTR + nj * 16) * 2);\
        _Pragma("unroll") for (int mi = 0; mi < 4; mi++)                       \
        _Pragma("unroll") for (int ni = 0; ni < 4; ni++)                       \
            mma_bf16(acc[mi][ni], af[mi], bf[ni]);                             \
    }

#define GEMM_MAINLOOP(Wb, ldk, KK, Xb)                                         \
    {                                                                          \
        const int nit = (KK) / 64;                                             \
        GEMM_CP(Wb, ldk, Xb, 0, 0);  CP_COMMIT();                              \
        GEMM_CP(Wb, ldk, Xb, 64, 1); CP_COMMIT();                              \
        int stg = 0;                                                           \
        for (int it = 0; it < nit; it++) {                                     \
            CP_WAIT1();                                                        \
            __syncthreads();                                                   \
            if (it + 2 < nit) {                                                \
                int st2 = stg + 2; if (st2 >= GST) st2 -= GST;                 \
                GEMM_CP(Wb, ldk, Xb, (it + 2) * 64, st2);                      \
            }                                                                  \
            CP_COMMIT();                                                       \
            GEMM_COMPUTE(stg);                                                 \
            if (++stg >= GST) stg -= GST;                                      \
        }                                                                      \
    }

// =============================================================================
// Merged GEMM1+GEMM2: grid.y 0..15 -> u/v (W_in, silu); 16..19 -> q/k (W_attn)
// =============================================================================
__global__ __launch_bounds__(256, 2) void gemm_uvqk_bf16(
    const float* __restrict__ b_in,
    const float* __restrict__ b_attn,
    const float* __restrict__ wq, const float* __restrict__ bq,
    const float* __restrict__ wk, const float* __restrict__ bk)
{
    GEMM_DECL();
    const __nv_bfloat16* xb = g_xb + (size_t)b * C_ * T_;
    const __nv_bfloat16* Ap = (m0 < 2 * E_)
        ? g_wi
        : g_wa - (size_t)(2 * E_) * C_;
    GEMM_MAINLOOP(Ap, C_, C_, xb);

    if (m0 < 2 * E_) {
        __nv_bfloat16* outp = (m0 < E_)
            ? g_u + (size_t)b * E_ * T_
            : g_v + (size_t)b * E_ * T_ - (size_t)E_ * T_;
#pragma unroll
        for (int mi = 0; mi < 4; mi++) {
            int m = m0 + wm + mi * 16 + g;
            float b0 = b_in[m], b1 = b_in[m + 8];
#pragma unroll
            for (int ni = 0; ni < 4; ni++) {
                int n = n0 + wn + ni * 8 + 2 * th4;
                float t0 = acc[mi][ni][0] + b0, t1 = acc[mi][ni][1] + b0;
                float t2 = acc[mi][ni][2] + b1, t3 = acc[mi][ni][3] + b1;
                unsigned w0 = packbf(silua(t0), silua(t1));
                unsigned w1 = packbf(silua(t2), silua(t3));
                *(unsigned*)(outp + (size_t)m * T_ + n)       = w0;
                *(unsigned*)(outp + (size_t)(m + 8) * T_ + n) = w1;
            }
        }
    } else {
        const int mq0 = m0 - 2 * E_;
        __nv_bfloat16* qp = g_q + (size_t)b * QK_ * T_;
        __nv_bfloat16* kp = g_k + (size_t)b * QK_ * T_;
#pragma unroll
        for (int mi = 0; mi < 4; mi++) {
            int m = mq0 + wm + mi * 16 + g;
            float bi0 = b_attn[m], bi1 = b_attn[m + 8];
            float wq0 = wq[m] * QSCALE_, bq0 = bq[m] * QSCALE_;
            float wk0 = wk[m], bk0 = bk[m];
            float wq1 = wq[m + 8] * QSCALE_, bq1 = bq[m + 8] * QSCALE_;
            float wk1 = wk[m + 8], bk1 = bk[m + 8];
#pragma unroll
            for (int ni = 0; ni < 4; ni++) {
                int n = n0 + wn + ni * 8 + 2 * th4;
                float z0 = acc[mi][ni][0] + bi0, z1 = acc[mi][ni][1] + bi0;
                float z2 = acc[mi][ni][2] + bi1, z3 = acc[mi][ni][3] + bi1;
                *(unsigned*)(qp + (size_t)m * T_ + n)       = packbf(z0 * wq0 + bq0, z1 * wq0 + bq0);
                *(unsigned*)(qp + (size_t)(m + 8) * T_ + n) = packbf(z2 * wq1 + bq1, z3 * wq1 + bq1);
                *(unsigned*)(kp + (size_t)m * T_ + n)       = packbf(z0 * wk0 + bk0, z1 * wk0 + bk0);
                *(unsigned*)(kp + (size_t)(m + 8) * T_ + n) = packbf(z2 * wk1 + bk1, z3 * wk1 + bk1);
            }
        }
    }
}

// =============================================================================
// Flash attention bf16, BQ=128 (8 warps x 16 rows), BKV=64,
// 3-stage cp.async KV pipeline, ONE barrier per tile, no-max exp2 softmax.
// Softmax exp INTERLEAVED with PV per j-group (MUFU overlaps tensor pipe).
// Q fragments hoisted; fused u-gating epilogue; 2 CTAs/SM.
// =============================================================================
#define QS2 136
#define KS2 72
#define KVB (192 * KS2 * 2)
#define QS_BYTES (64 * QS2 * 2)
#define AST 3
#define ATTN_SMEM (QS_BYTES + AST * KVB)

__global__ __launch_bounds__(256, 2) void attn_bf16_kernel()
{
    extern __shared__ __align__(16) char dsm[];
    unsigned short* qs = (unsigned short*)dsm;
    unsigned short* ks = (unsigned short*)(dsm + QS_BYTES);
    unsigned short* vs = ks + 64 * KS2;
    float* os = (float*)(dsm + QS_BYTES);   // epilogue alias

    const int b  = blockIdx.z;
    const int h  = blockIdx.y;
    const int qt = blockIdx.x;
    const int tid = threadIdx.x;
    const int lane = tid & 31, warp = tid >> 5;
    const int g = lane >> 2, th4 = lane & 3;
    const int wq = warp * 16;

    const __nv_bfloat16* qbase = g_q + (size_t)(b * QK_ + h * HD_) * T_;
    const __nv_bfloat16* kbase = g_k + (size_t)(b * QK_ + h * HD_) * T_;
    const __nv_bfloat16* vbase = g_v + (size_t)(b * E_ + h * EV_) * T_;

    const unsigned qs_b = (unsigned)__cvta_generic_to_shared(qs);
    const unsigned ks_b = (unsigned)__cvta_generic_to_shared(ks);
    const unsigned vs_b = (unsigned)__cvta_generic_to_shared(vs);

    const unsigned qa0 = qs_b + ((((lane >> 4) << 3) + (lane & 7)) * QS2 + wq + (lane & 8)) * 2;
    const unsigned ka0 = ks_b + (((lane & 7) + ((lane >> 3) & 1) * 8) * KS2 + ((lane >> 4) & 1) * 8) * 2;
    const unsigned va0 = vs_b + (((lane & 7) + ((lane >> 4) & 1) * 8) * KS2 + (lane & 8)) * 2;

#pragma unroll
    for (int p = 0; p < 4; p++) {
        int idx = tid + 256 * p;
        int d  = idx >> 4;
        int q8 = (idx & 15) << 3;
        *(uint4*)&qs[d * QS2 + q8] =
            *(const uint4*)(qbase + (size_t)d * T_ + qt * 128 + q8);
    }

#define ATTN_CP_KV(kt0, st)                                                    \
    _Pragma("unroll") for (int p = 0; p < 2; p++) {                            \
        int idx = tid + 256 * p;                                               \
        int d  = idx >> 3;                                                     \
        int c8 = (idx & 7) << 3;                                               \
        cp16(ks_b + (st) * KVB + (d * KS2 + c8) * 2,                           \
             kbase + (size_t)d * T_ + (kt0) + c8);                             \
    }                                                                          \
    _Pragma("unroll") for (int p = 0; p < 4; p++) {                            \
        int idx = tid + 256 * p;                                               \
        int e  = idx >> 3;                                                     \
        int c8 = (idx & 7) << 3;                                               \
        cp16(vs_b + (st) * KVB + (e * KS2 + c8) * 2,                           \
             vbase + (size_t)e * T_ + (kt0) + c8);                             \
    }

    float o[16][4];
#pragma unroll
    for (int e = 0; e < 16; e++)
#pragma unroll
        for (int r = 0; r < 4; r++) o[e][r] = 0.f;
    float l_0 = 0.f, l_1 = 0.f;

    ATTN_CP_KV(0, 0);   CP_COMMIT();
    ATTN_CP_KV(64, 1);  CP_COMMIT();
    __syncthreads();

    unsigned aq[4][4];
#pragma unroll
    for (int kd = 0; kd < 4; kd++)
        ldsm4t(aq[kd][0], aq[kd][1], aq[kd][2], aq[kd][3], qa0 + kd * 16 * QS2 * 2);

    int stage = 0;
    for (int kt = 0; kt < 16; kt++) {
        CP_WAIT1();
        __syncthreads();
        if (kt + 2 < 16) {
            int st2 = stage + 2; if (st2 >= AST) st2 -= AST;
            ATTN_CP_KV((kt + 2) * 64, st2);
        }
        CP_COMMIT();
        const unsigned stoff = (unsigned)stage * KVB;

        // ---- S = Q K^T ----
        float s[8][4];
#pragma unroll
        for (int ni = 0; ni < 8; ni++)
#pragma unroll
            for (int r = 0; r < 4; r++) s[ni][r] = 0.f;
#pragma unroll
        for (int kd = 0; kd < 4; kd++) {
#pragma unroll
            for (int kvj = 0; kvj < 4; kvj++) {
                unsigned r0, r1, r2, r3;
                ldsm4t(r0, r1, r2, r3, ka0 + stoff + (kd * 16 * KS2 + kvj * 16) * 2);
                unsigned b0[2] = {r0, r1}, b1[2] = {r2, r3};
                mma_bf16(s[2 * kvj],     aq[kd], b0);
                mma_bf16(s[2 * kvj + 1], aq[kd], b1);
            }
        }

        // ---- softmax exp interleaved with PV per j-group ----
#pragma unroll
        for (int j = 0; j < 4; j++) {
            float p00 = ex2a(s[2 * j][0]),     p01 = ex2a(s[2 * j][1]);
            float p02 = ex2a(s[2 * j][2]),     p03 = ex2a(s[2 * j][3]);
            float p10 = ex2a(s[2 * j + 1][0]), p11 = ex2a(s[2 * j + 1][1]);
            float p12 = ex2a(s[2 * j + 1][2]), p13 = ex2a(s[2 * j + 1][3]);
            l_0 += p00 + p01 + p10 + p11;
            l_1 += p02 + p03 + p12 + p13;
            unsigned pf[4];
            pf[0] = packbf(p00, p01);
            pf[1] = packbf(p02, p03);
            pf[2] = packbf(p10, p11);
            pf[3] = packbf(p12, p13);
#pragma unroll
            for (int ej = 0; ej < 8; ej++) {
                unsigned r0, r1, r2, r3;
                ldsm4(r0, r1, r2, r3, va0 + stoff + (ej * 16 * KS2 + j * 16) * 2);
                unsigned b0[2] = {r0, r1}, b1[2] = {r2, r3};
                mma_bf16(o[2 * ej],     pf, b0);
                mma_bf16(o[2 * ej + 1], pf, b1);
            }
        }
        if (++stage >= AST) stage -= AST;
    }

    l_0 += __shfl_xor_sync(0xffffffffu, l_0, 1);
    l_0 += __shfl_xor_sync(0xffffffffu, l_0, 2);
    l_1 += __shfl_xor_sync(0xffffffffu, l_1, 1);
    l_1 += __shfl_xor_sync(0xffffffffu, l_1, 2);
    float inv0 = rcpa(l_0), inv1 = rcpa(l_1);
#pragma unroll
    for (int e = 0; e < 16; e++) {
        o[e][0] *= inv0; o[e][1] *= inv0;
        o[e][2] *= inv1; o[e][3] *= inv1;
    }

    const __nv_bfloat16* ubase = g_u + (size_t)(b * E_ + h * EV_) * T_ + qt * 128;
    __nv_bfloat16* wbase = g_w + (size_t)(b * E_ + h * EV_) * T_ + qt * 128;
#pragma unroll
    for (int eh = 0; eh < 2; eh++) {
        __syncthreads();
#pragma unroll
        for (int et = eh * 8; et < eh * 8 + 8; et++) {
            int ec = et * 8 + 2 * th4 - eh * 64;
            os[ec * QS2 + wq + g]           = o[et][0];
            os[(ec + 1) * QS2 + wq + g]     = o[et][1];
            os[ec * QS2 + wq + g + 8]       = o[et][2];
            os[(ec + 1) * QS2 + wq + g + 8] = o[et][3];
        }
        __syncthreads();
#pragma unroll
        for (int p = 0; p < 4; p++) {
            int idx = tid + 256 * p;
            int e  = idx >> 4;
            int t8 = (idx & 15) << 3;
            int eg = eh * 64 + e;
            uint4 uv = *(const uint4*)(ubase + (size_t)eg * T_ + t8);
            const __nv_bfloat162* up = (const __nv_bfloat162*)&uv;
            const float* orow = os + e * QS2 + t8;
            float2 u0 = __bfloat1622float2(up[0]);
            float2 u1 = __bfloat1622float2(up[1]);
            float2 u2 = __bfloat1622float2(up[2]);
            float2 u3 = __bfloat1622float2(up[3]);
            uint4 wv = {
                packbf(u0.x * orow[0], u0.y * orow[1]),
                packbf(u1.x * orow[2], u1.y * orow[3]),
                packbf(u2.x * orow[4], u2.y * orow[5]),
                packbf(u3.x * orow[6], u3.y * orow[7])};
            *(uint4*)(wbase + (size_t)eg * T_ + t8) = wv;
        }
    }
}

// =============================================================================
// GEMM3: y = x + b_out + W_out @ w ; also accumulates ss[b][t] += y^2 (atomics)
// =============================================================================
__global__ __launch_bounds__(256, 2) void gemm_out_bf16(
    const float* __restrict__ x, const float* __restrict__ bias)
{
    GEMM_DECL();
    const __nv_bfloat16* wb = g_w + (size_t)b * E_ * T_;
    GEMM_MAINLOOP(g_wo, E_, E_, wb);
    const float* xb = x + (size_t)b * C_ * T_;
    float* yp = g_y + (size_t)b * C_ * T_;
    float* ssp = g_ss + (size_t)b * T_;
    float ss0[4], ss1[4];
#pragma unroll
    for (int ni = 0; ni < 4; ni++) { ss0[ni] = 0.f; ss1[ni] = 0.f; }
#pragma unroll
    for (int mi = 0; mi < 4; mi++) {
        int m = m0 + wm + mi * 16 + g;
        float bo0 = bias[m], bo1 = bias[m + 8];
#pragma unroll
        for (int ni = 0; ni < 4; ni++) {
            int n = n0 + wn + ni * 8 + 2 * th4;
            float2 x0 = *(const float2*)(xb + (size_t)m * T_ + n);
            float2 x1 = *(const float2*)(xb + (size_t)(m + 8) * T_ + n);
            float2 y0 = {acc[mi][ni][0] + bo0 + x0.x, acc[mi][ni][1] + bo0 + x0.y};
            float2 y1 = {acc[mi][ni][2] + bo1 + x1.x, acc[mi][ni][3] + bo1 + x1.y};
            ss0[ni] += y0.x * y0.x + y1.x * y1.x;
            ss1[ni] += y0.y * y0.y + y1.y * y1.y;
            *(float2*)(yp + (size_t)m * T_ + n)       = y0;
            *(float2*)(yp + (size_t)(m + 8) * T_ + n) = y1;
        }
    }
#pragma unroll
    for (int ni = 0; ni < 4; ni++) {
        int n = n0 + wn + ni * 8 + 2 * th4;
        atomicAdd(ssp + n,     ss0[ni]);
        atomicAdd(ssp + n + 1, ss1[ni]);
    }
}

// =============================================================================
// RMSNorm over C: ss precomputed by gemm_out, single read+write pass
// =============================================================================
__global__ __launch_bounds__(256) void rms2_kernel(
    const float* __restrict__ gamma, float* __restrict__ out)
{
    const int b = blockIdx.y;
    const int tseg = threadIdx.x & 31, cseg = threadIdx.x >> 5;
    const int t = blockIdx.x * 32 + tseg;
    const float* yb = g_y + (size_t)b * C_ * T_ + t;
    float r = rsqrtf(g_ss[(size_t)b * T_ + t] * (1.f / C_) + 1e-5f);
    float* op = out + (size_t)b * C_ * T_ + t;
#pragma unroll 8
    for (int c = cseg * 64; c < cseg * 64 + 64; c++) {
        op[(size_t)c * T_] = yb[(size_t)c * T_] * r * gamma[c];
    }
}

// =============================================================================
// launch
// =============================================================================
extern "C" void kernel_launch(void* const* d_in, const int* in_sizes, int n_in,
                              void* d_out, int out_size)
{
    const float* x      = (const float*)d_in[0];
    const float* W_in   = (const float*)d_in[1];
    const float* b_in   = (const float*)d_in[2];
    const float* W_attn = (const float*)d_in[3];
    const float* b_attn = (const float*)d_in[4];
    const float* w_q    = (const float*)d_in[5];
    const float* b_q    = (const float*)d_in[6];
    const float* w_k    = (const float*)d_in[7];
    const float* b_k    = (const float*)d_in[8];
    const float* W_out  = (const float*)d_in[9];
    const float* b_out  = (const float*)d_in[10];
    const float* gamma  = (const float*)d_in[11];
    float* out = (float*)d_out;

    cudaFuncSetAttribute(gemm_uvqk_bf16,
                         cudaFuncAttributeMaxDynamicSharedMemorySize, GEMM_SMEM);
    cudaFuncSetAttribute(gemm_out_bf16,
                         cudaFuncAttributeMaxDynamicSharedMemorySize, GEMM_SMEM);
    cudaFuncSetAttribute(attn_bf16_kernel,
                         cudaFuncAttributeMaxDynamicSharedMemorySize, ATTN_SMEM);

    void* pss = nullptr;
    cudaGetSymbolAddress(&pss, g_ss);
    cudaMemsetAsync(pss, 0, (size_t)B_ * T_ * sizeof(float));

    conv_all<<<CV3, 256>>>(W_in, W_attn, W_out, x);

    gemm_uvqk_bf16<<<dim3(T_ / 128, 20, B_), 256, GEMM_SMEM>>>(
        b_in, b_attn, w_q, b_q, w_k, b_k);
    attn_bf16_kernel<<<dim3(T_ / 128, H_, B_), 256, ATTN_SMEM>>>();
    gemm_out_bf16<<<dim3(T_ / 128, C_ / 128, B_), 256, GEMM_SMEM>>>(x, b_out);
    rms2_kernel<<<dim3(T_ / 32, B_), 256>>>(gamma, out);
}